// round 12
// baseline (speedup 1.0000x reference)
#include <cuda_runtime.h>
#include <cuda_bf16.h>
#include <math.h>
#include <stdint.h>

#define Bb  8
#define Ss  4096
#define Dd  512
#define Pp  128
#define Ll  4
#define DFf 2048
#define DHh 256
#define CC  2
#define BS  (Bb*Ss)
#define KVS 8

// ===================== PTX helpers (sm_90 core features only) =====================
__device__ __forceinline__ uint32_t smem_to_u32(const void* p) {
    uint32_t a;
    asm("{ .reg .u64 t; cvta.to.shared.u64 t, %1; cvt.u32.u64 %0, t; }" : "=r"(a) : "l"(p));
    return a;
}
#define MBARRIER_INIT(m, c) \
    asm volatile("mbarrier.init.shared.b64 [%0], %1;" :: "r"((uint32_t)(m)), "r"((uint32_t)(c)) : "memory")
#define MBARRIER_EXPECT_TX(m, b) \
    asm volatile("mbarrier.arrive.expect_tx.shared.b64 _, [%0], %1;" :: "r"((uint32_t)(m)), "r"((uint32_t)(b)) : "memory")
#define MBARRIER_ARRIVE(m) \
    asm volatile("mbarrier.arrive.shared.b64 _, [%0];" :: "r"((uint32_t)(m)) : "memory")
#define MBARRIER_WAIT_PARITY(m, par) do { \
    uint32_t _m=(uint32_t)(m), _p=(uint32_t)(par), _d; \
    asm volatile("{\n\t.reg .pred p;\n\tmbarrier.try_wait.parity.acquire.cta.shared::cta.b64 p, [%1], %2;\n\tselp.b32 %0,1,0,p;\n\t}" \
        : "=r"(_d) : "r"(_m), "r"(_p) : "memory"); \
    if (!_d) { \
        asm volatile("{\n\t.reg .pred P1;\n\tWL_%=:\n\tmbarrier.try_wait.parity.acquire.cta.shared::cta.b64 P1, [%0], %1, 0x989680;\n\t@P1 bra.uni WD_%=;\n\tbra.uni WL_%=;\n\tWD_%=:\n\t}" \
            :: "r"(_m), "r"(_p) : "memory"); \
    } \
} while(0)
__device__ __forceinline__ void bulk_g2s(uint32_t dst, const void* src, uint32_t bytes, uint32_t mbar){
    asm volatile("cp.async.bulk.shared::cluster.global.mbarrier::complete_tx::bytes [%0], [%1], %2, [%3];"
        :: "r"(dst), "l"(src), "r"(bytes), "r"(mbar) : "memory");
}
__device__ __forceinline__ void ldsm4(uint32_t* r, uint32_t addr){
    asm volatile("ldmatrix.sync.aligned.m8n8.x4.shared.b16 {%0,%1,%2,%3}, [%4];"
        : "=r"(r[0]),"=r"(r[1]),"=r"(r[2]),"=r"(r[3]) : "r"(addr));
}
__device__ __forceinline__ void mma_bf16(float* d, const uint32_t* a, const uint32_t* b){
    asm volatile("mma.sync.aligned.m16n8k16.row.col.f32.bf16.bf16.f32 "
        "{%0,%1,%2,%3}, {%4,%5,%6,%7}, {%8,%9}, {%0,%1,%2,%3};"
        : "+f"(d[0]),"+f"(d[1]),"+f"(d[2]),"+f"(d[3])
        : "r"(a[0]),"r"(a[1]),"r"(a[2]),"r"(a[3]), "r"(b[0]),"r"(b[1]));
}

// ===================== chunk-packed layout =====================
__device__ __forceinline__ long cidx(int KC, int pl, int blk, int r, int k){
    return (((long)(blk*2 + pl)*KC + (k>>5)) << 12) + ((((k>>3)&3)*128 + r) << 3) + (k&7);
}

// ===================== device globals =====================
__device__ __align__(256) __nv_bfloat16 g_hS [2*(size_t)BS*Dd];
__device__ __align__(256) __nv_bfloat16 g_qS [2*(size_t)BS*Dd];
__device__ __align__(256) __nv_bfloat16 g_vT [2*(size_t)BS*Dd];
__device__ __align__(256) __nv_bfloat16 g_tS [2*(size_t)BS*Dd];
__device__ __align__(256) __nv_bfloat16 g_pqS[2*(size_t)BS*Pp];
__device__ __align__(256) __nv_bfloat16 g_pkT[2*(size_t)BS*Pp];
__device__ __align__(256) __nv_bfloat16 g_mS [2*(size_t)BS*DFf];
__device__ __align__(256) __nv_bfloat16 g_kvtS[(size_t)Bb*2*Dd*Pp];
__device__ __align__(256) __nv_bfloat16 g_wv[(size_t)Ll*2*Dd*Dd];
__device__ __align__(256) __nv_bfloat16 g_wo[(size_t)Ll*2*Dd*Dd];
__device__ __align__(256) __nv_bfloat16 g_w1[(size_t)Ll*2*DFf*Dd];
__device__ __align__(256) __nv_bfloat16 g_w2[(size_t)Ll*2*Dd*DFf];
__device__ __align__(256) __nv_bfloat16 g_wqf[(size_t)Ll*2*Pp*Dd];
__device__ __align__(256) __nv_bfloat16 g_wkf[(size_t)Ll*2*Pp*Dd];
__device__ float g_bqf[Ll*Pp];
__device__ float g_bkf[Ll*Pp];
__device__ float g_kvp[(size_t)Bb*KVS*Pp*Dd];
__device__ float g_ks [Bb*Pp];
__device__ float g_z  [BS];
__device__ float g_pp [Bb*32*Dd];
__device__ float g_pool[Bb*Dd];
__device__ float g_h1 [Bb*DHh];

__device__ __forceinline__ float gelu_tanh(float x){
    float u = 0.7978845608028654f*(x + 0.044715f*x*x*x);
    return 0.5f*x*(1.0f + tanhf(u));
}

// ===================== bulk-pipelined split-bf16 HMMA GEMM =====================
#define NSTG 3

// EPI 0:+bias 1:+bias,elu+1 2:+bias,gelu 3:*1/(aux+eps)
// TOUT 0:chunked [M,N], 1:transposed chunked [N rows][Ss]
// PASSES 3 only (PASSES=2 measured at rel_err 6e-3 — activation-lo is load-bearing)
template<int EPI, int TOUT, int PASSES>
__global__ void __launch_bounds__(256)
gemm_mma(const __nv_bfloat16* __restrict__ A, int KCa,
         const __nv_bfloat16* __restrict__ Bw, int KCb, long b_batch,
         const float* __restrict__ bias, const float* __restrict__ aux,
         __nv_bfloat16* __restrict__ C, int N, int K)
{
    constexpr uint32_t STGB = (PASSES == 3) ? 65536u : 49152u;
    constexpr uint32_t BOFF = (PASSES == 3) ? 32768u : 16384u;
    extern __shared__ __align__(1024) char smem[];
    const uint32_t sb = smem_to_u32(smem);
    const int tid = threadIdx.x, wid = tid >> 5, lane = tid & 31;
    const int rowblk = blockIdx.z*gridDim.y + blockIdx.y;
    const int nblk = blockIdx.x;
    const int row0 = rowblk*128, col0 = nblk*128;
    const int niter = K >> 6;
    const uint32_t FULL0 = sb, EMPTY0 = sb + 32;
    const uint32_t STG0 = sb + 1024;
    const __nv_bfloat16* Bt = Bw + (long)blockIdx.z*b_batch;

    if (tid == 0){
        #pragma unroll
        for (int s = 0; s < NSTG; ++s){ MBARRIER_INIT(FULL0+8*s, 1); MBARRIER_INIT(EMPTY0+8*s, 256); }
    }
    __syncthreads();

    auto issue = [&](int j){
        const int s = j % NSTG;
        if (j >= NSTG) MBARRIER_WAIT_PARITY(EMPTY0+8*s, ((j/NSTG)-1)&1);
        MBARRIER_EXPECT_TX(FULL0+8*s, STGB);
        const uint32_t dst = STG0 + s*STGB;
        bulk_g2s(dst, A + (((long)(rowblk*2)*KCa + j*2) << 12), 16384u, FULL0+8*s);
        if (PASSES == 3)
            bulk_g2s(dst + 16384, A + (((long)(rowblk*2+1)*KCa + j*2) << 12), 16384u, FULL0+8*s);
        #pragma unroll
        for (int pl = 0; pl < 2; ++pl)
            bulk_g2s(dst + BOFF + pl*16384,
                     Bt + (((long)(nblk*2+pl)*KCb + j*2) << 12), 16384u, FULL0+8*s);
    };
    if (tid == 0){
        const int pro = (niter < NSTG-1) ? niter : NSTG-1;
        for (int j = 0; j < pro; ++j) issue(j);
    }

    float acc[2][8][4];
    #pragma unroll
    for (int mt=0;mt<2;mt++)
        #pragma unroll
        for (int ni=0;ni<8;ni++)
            #pragma unroll
            for (int r=0;r<4;r++) acc[mt][ni][r]=0.f;

    const int wm = (wid >> 1)*32, wn = (wid & 1)*64;
    const int a_mrow = wm + ((lane>>3)&1)*8 + (lane&7);
    const int a_kc   = (lane>>4);
    const int b_nrow = wn + ((lane>>4)&1)*8 + (lane&7);
    const int b_kc   = ((lane>>3)&1);

    for (int it = 0; it < niter; ++it){
        const int s = it % NSTG;
        if (tid == 0 && it + NSTG-1 < niter) issue(it + NSTG-1);
        MBARRIER_WAIT_PARITY(FULL0+8*s, (it/NSTG)&1);
        const uint32_t stg = STG0 + s*STGB;
        #pragma unroll
        for (int step = 0; step < 4; ++step){
            const int ga = a_kc + 2*step, gb = b_kc + 2*step;
            uint32_t ah[2][4], al[2][4], bh[4][4], bl[4][4];
            #pragma unroll
            for (int mt = 0; mt < 2; ++mt){
                const uint32_t aoff = stg + (uint32_t)((ga>>2)*8192 + (((ga&3)*128) + a_mrow + mt*16)*16);
                ldsm4(ah[mt], aoff);
                if (PASSES == 3) ldsm4(al[mt], aoff + 16384);
            }
            #pragma unroll
            for (int nt4 = 0; nt4 < 4; ++nt4){
                const uint32_t boff = stg + BOFF + (uint32_t)((gb>>2)*8192 + (((gb&3)*128) + b_nrow + nt4*16)*16);
                ldsm4(bh[nt4], boff);
                ldsm4(bl[nt4], boff + 16384);
            }
            #pragma unroll
            for (int mt = 0; mt < 2; ++mt)
                #pragma unroll
                for (int ni = 0; ni < 8; ++ni)
                    mma_bf16(acc[mt][ni], ah[mt], bh[ni>>1] + (ni&1)*2);
            if (PASSES == 3){
                #pragma unroll
                for (int mt = 0; mt < 2; ++mt)
                    #pragma unroll
                    for (int ni = 0; ni < 8; ++ni)
                        mma_bf16(acc[mt][ni], al[mt], bh[ni>>1] + (ni&1)*2);
            }
            #pragma unroll
            for (int mt = 0; mt < 2; ++mt)
                #pragma unroll
                for (int ni = 0; ni < 8; ++ni)
                    mma_bf16(acc[mt][ni], ah[mt], bl[ni>>1] + (ni&1)*2);
        }
        MBARRIER_ARRIVE(EMPTY0+8*s);
    }

    // ---- epilogue ----
    float bv0[8], bv1[8];
    if (EPI != 3){
        #pragma unroll
        for (int ni = 0; ni < 8; ++ni){
            const int col = col0 + wn + ni*8 + (lane&3)*2;
            bv0[ni] = bias[col]; bv1[ni] = bias[col+1];
        }
    }

    if (TOUT == 0){
        const int KCo = N >> 5;
        #pragma unroll
        for (int mt = 0; mt < 2; ++mt){
            #pragma unroll
            for (int h = 0; h < 2; ++h){
                const long row = row0 + wm + mt*16 + h*8 + (lane>>2);
                float sc = 1.f;
                if (EPI == 3) sc = 1.f/(aux[row] + 1e-6f);
                const int r = (int)(row & 127);
                #pragma unroll
                for (int ni = 0; ni < 8; ++ni){
                    const int col = col0 + wn + ni*8 + (lane&3)*2;
                    float c0 = acc[mt][ni][2*h], c1 = acc[mt][ni][2*h+1];
                    if (EPI != 3){ c0 += bv0[ni]; c1 += bv1[ni]; }
                    if (EPI == 1){ c0 = (c0>0.f)?(c0+1.f):expf(c0); c1 = (c1>0.f)?(c1+1.f):expf(c1); }
                    if (EPI == 2){ c0 = gelu_tanh(c0); c1 = gelu_tanh(c1); }
                    if (EPI == 3){ c0 *= sc; c1 *= sc; }
                    __nv_bfloat16 h0 = __float2bfloat16(c0), h1 = __float2bfloat16(c1);
                    __nv_bfloat162 vh; vh.x = h0; vh.y = h1;
                    __nv_bfloat162 vl;
                    vl.x = __float2bfloat16(c0 - __bfloat162float(h0));
                    vl.y = __float2bfloat16(c1 - __bfloat162float(h1));
                    *(__nv_bfloat162*)(C + cidx(KCo, 0, rowblk, r, col)) = vh;
                    *(__nv_bfloat162*)(C + cidx(KCo, 1, rowblk, r, col)) = vl;
                }
            }
        }
    } else {
        #pragma unroll
        for (int mt = 0; mt < 2; ++mt)
            #pragma unroll
            for (int ni = 0; ni < 8; ++ni){
                #pragma unroll
                for (int h = 0; h < 2; ++h){
                    float c0 = acc[mt][ni][2*h] + bv0[ni];
                    float c1 = acc[mt][ni][2*h+1] + bv1[ni];
                    if (EPI == 1){ c0 = (c0>0.f)?(c0+1.f):expf(c0); c1 = (c1>0.f)?(c1+1.f):expf(c1); }
                    acc[mt][ni][2*h] = c0; acc[mt][ni][2*h+1] = c1;
                }
            }
        __syncthreads();
        __nv_bfloat16* sT = (__nv_bfloat16*)(smem + 1024);   // [128 col][136 tok]
        const int st0 = (int)(row0 & (Ss-1));
        const int cb = col0 >> 7;
        const int KCss = Ss >> 5;
        __nv_bfloat16* tB = C + (long)(row0 >> 12)*2*(long)N*Ss;
        #pragma unroll
        for (int pl = 0; pl < 2; ++pl){
            #pragma unroll
            for (int mt = 0; mt < 2; ++mt){
                #pragma unroll
                for (int h = 0; h < 2; ++h){
                    const int tok = wm + mt*16 + h*8 + (lane>>2);
                    #pragma unroll
                    for (int ni = 0; ni < 8; ++ni){
                        const int col = wn + ni*8 + (lane&3)*2;
                        float c0 = acc[mt][ni][2*h], c1 = acc[mt][ni][2*h+1];
                        __nv_bfloat16 h0 = __float2bfloat16(c0), h1 = __float2bfloat16(c1);
                        if (pl){
                            h0 = __float2bfloat16(c0 - __bfloat162float(h0));
                            h1 = __float2bfloat16(c1 - __bfloat162float(h1));
                        }
                        sT[col*136 + tok]     = h0;
                        sT[(col+1)*136 + tok] = h1;
                    }
                }
            }
            __syncthreads();
            #pragma unroll
            for (int j = 0; j < 8; ++j){
                const int idx = j*256 + tid;
                const int oct = idx >> 7, n = idx & 127;
                uint4 v = *(const uint4*)(sT + n*136 + oct*8);
                const int st = st0 + oct*8;
                long e = (((long)(cb*2+pl)*KCss + (st>>5)) << 12) + ((((st>>3)&3)*128 + n) << 3);
                *(uint4*)(tB + e) = v;
            }
            __syncthreads();
        }
    }
}

// ===================== kv gemm: kv^T[b] = vT[b] @ pkT[b]^T, split-K fp32 partials =====================
#define STGB3 65536
__global__ void __launch_bounds__(256)
gemm_kv(const __nv_bfloat16* __restrict__ vT, const __nv_bfloat16* __restrict__ pkT,
        float* __restrict__ part)
{
    extern __shared__ __align__(1024) char smem[];
    const uint32_t sb = smem_to_u32(smem);
    const int tid = threadIdx.x, wid = tid >> 5, lane = tid & 31;
    const int bz = blockIdx.z, b = bz >> 3, sp = bz & (KVS-1);
    const int ablk = blockIdx.y, row0 = ablk*128;
    const int niter = (Ss/KVS) >> 6;      // 8
    const int kchunk0 = sp*((Ss/KVS) >> 5);
    const uint32_t FULL0 = sb, EMPTY0 = sb + 32;
    const uint32_t STG0 = sb + 1024;
    const __nv_bfloat16* A  = vT  + (long)b*2*Dd*Ss;
    const __nv_bfloat16* Bp = pkT + (long)b*2*Pp*Ss;

    if (tid == 0){
        #pragma unroll
        for (int s = 0; s < NSTG; ++s){ MBARRIER_INIT(FULL0+8*s, 1); MBARRIER_INIT(EMPTY0+8*s, 256); }
    }
    __syncthreads();

    auto issue = [&](int j){
        const int s = j % NSTG;
        if (j >= NSTG) MBARRIER_WAIT_PARITY(EMPTY0+8*s, ((j/NSTG)-1)&1);
        MBARRIER_EXPECT_TX(FULL0+8*s, 65536u);
        const uint32_t dst = STG0 + s*STGB3;
        #pragma unroll
        for (int pl = 0; pl < 2; ++pl){
            bulk_g2s(dst + pl*16384,
                     A  + (((long)(ablk*2+pl)*(Ss>>5) + kchunk0 + j*2) << 12), 16384u, FULL0+8*s);
            bulk_g2s(dst + 32768 + pl*16384,
                     Bp + (((long)pl*(Ss>>5) + kchunk0 + j*2) << 12), 16384u, FULL0+8*s);
        }
    };
    if (tid == 0){ for (int j = 0; j < NSTG-1; ++j) issue(j); }

    float acc[2][8][4];
    #pragma unroll
    for (int mt=0;mt<2;mt++)
        #pragma unroll
        for (int ni=0;ni<8;ni++)
            #pragma unroll
            for (int r=0;r<4;r++) acc[mt][ni][r]=0.f;

    const int wm = (wid >> 1)*32, wn = (wid & 1)*64;
    const int a_mrow = wm + ((lane>>3)&1)*8 + (lane&7);
    const int a_kc   = (lane>>4);
    const int b_nrow = wn + ((lane>>4)&1)*8 + (lane&7);
    const int b_kc   = ((lane>>3)&1);

    for (int it = 0; it < niter; ++it){
        const int s = it % NSTG;
        if (tid == 0 && it + NSTG-1 < niter) issue(it + NSTG-1);
        MBARRIER_WAIT_PARITY(FULL0+8*s, (it/NSTG)&1);
        const uint32_t stg = STG0 + s*STGB3;
        #pragma unroll
        for (int step = 0; step < 4; ++step){
            const int ga = a_kc + 2*step, gb = b_kc + 2*step;
            uint32_t ah[2][4], al[2][4], bh[4][4], bl[4][4];
            #pragma unroll
            for (int mt = 0; mt < 2; ++mt){
                const uint32_t aoff = stg + (uint32_t)((ga>>2)*8192 + (((ga&3)*128) + a_mrow + mt*16)*16);
                ldsm4(ah[mt], aoff);
                ldsm4(al[mt], aoff + 16384);
            }
            #pragma unroll
            for (int nt4 = 0; nt4 < 4; ++nt4){
                const uint32_t boff = stg + 32768 + (uint32_t)((gb>>2)*8192 + (((gb&3)*128) + b_nrow + nt4*16)*16);
                ldsm4(bh[nt4], boff);
                ldsm4(bl[nt4], boff + 16384);
            }
            #pragma unroll
            for (int mt = 0; mt < 2; ++mt)
                #pragma unroll
                for (int ni = 0; ni < 8; ++ni)
                    mma_bf16(acc[mt][ni], ah[mt], bh[ni>>1] + (ni&1)*2);
            #pragma unroll
            for (int mt = 0; mt < 2; ++mt)
                #pragma unroll
                for (int ni = 0; ni < 8; ++ni)
                    mma_bf16(acc[mt][ni], al[mt], bh[ni>>1] + (ni&1)*2);
            #pragma unroll
            for (int mt = 0; mt < 2; ++mt)
                #pragma unroll
                for (int ni = 0; ni < 8; ++ni)
                    mma_bf16(acc[mt][ni], ah[mt], bl[ni>>1] + (ni&1)*2);
        }
        MBARRIER_ARRIVE(EMPTY0+8*s);
    }

    float* Cb = part + (long)bz*Dd*Pp;
    #pragma unroll
    for (int mt = 0; mt < 2; ++mt){
        #pragma unroll
        for (int h = 0; h < 2; ++h){
            const int row = row0 + wm + mt*16 + h*8 + (lane>>2);
            #pragma unroll
            for (int ni = 0; ni < 8; ++ni){
                const int col = wn + ni*8 + (lane&3)*2;
                *(float2*)(Cb + (long)row*Pp + col) =
                    make_float2(acc[mt][ni][2*h], acc[mt][ni][2*h+1]);
            }
        }
    }
}

// reduce partials -> kvtS chunked [D rows][P] per batch
__global__ void reduce_kvt(const float* __restrict__ part, __nv_bfloat16* __restrict__ kvt)
{
    long i = (long)blockIdx.x*256 + threadIdx.x;
    int b = (int)(i / (Dd*Pp)); int r0 = (int)(i % (Dd*Pp));
    int d = r0 >> 7, p = r0 & 127;
    const float* q = part + ((long)b*KVS)*Dd*Pp + r0;
    float s = 0.f;
    #pragma unroll
    for (int j = 0; j < KVS; j++) s += q[(long)j*Dd*Pp];
    __nv_bfloat16 h = __float2bfloat16(s);
    __nv_bfloat16* base = kvt + (long)b*2*Dd*Pp;
    base[cidx(4, 0, d>>7, d&127, p)] = h;
    base[cidx(4, 1, d>>7, d&127, p)] = __float2bfloat16(s - __bfloat162float(h));
}

// ===================== weight conversion =====================
__global__ void wconv(const float* __restrict__ W, __nv_bfloat16* __restrict__ out, int K, int N)
{
    __shared__ float t[32][33];
    const int n0 = blockIdx.x*32, k0 = blockIdx.y*32, l = blockIdx.z;
    const float* Wl = W + (long)l*K*N;
    __nv_bfloat16* ob = out + (long)l*2*N*K;
    const int KC = K >> 5;
    for (int i = threadIdx.y; i < 32; i += 8)
        t[i][threadIdx.x] = Wl[(long)(k0+i)*N + n0 + threadIdx.x];
    __syncthreads();
    for (int i = threadIdx.y; i < 32; i += 8) {
        float v = t[threadIdx.x][i];
        const int n = n0 + i, k = k0 + threadIdx.x;
        __nv_bfloat16 h = __float2bfloat16(v);
        ob[cidx(KC, 0, n>>7, n&127, k)] = h;
        ob[cidx(KC, 1, n>>7, n&127, k)] = __float2bfloat16(v - __bfloat162float(h));
    }
}

// folded feature weights
__global__ void wfold(const float* __restrict__ Wq, const float* __restrict__ Wk,
                      const float* __restrict__ Wf,
                      __nv_bfloat16* __restrict__ oq, __nv_bfloat16* __restrict__ ok)
{
    const int which = blockIdx.z & 1, l = blockIdx.z >> 1;
    const float* Wa  = (which ? Wk : Wq) + (long)l*Dd*Dd;
    const float* Wfl = Wf + (long)l*Dd*Pp;
    __nv_bfloat16* out = (which ? ok : oq) + (long)l*2*Pp*Dd;
    const int p0 = blockIdx.x*32, c0 = blockIdx.y*32;
    __shared__ float a[32][33], bsm[32][33];
    const int tx = threadIdx.x, ty = threadIdx.y;
    float acc[4] = {0.f,0.f,0.f,0.f};
    for (int m0 = 0; m0 < Dd; m0 += 32){
        for (int i = ty; i < 32; i += 8) a[i][tx]   = Wa[(long)(c0+i)*Dd + m0+tx];
        for (int i = ty; i < 32; i += 8) bsm[i][tx] = Wfl[(long)(m0+i)*Pp + p0+tx];
        __syncthreads();
        #pragma unroll
        for (int mm = 0; mm < 32; ++mm){
            float bv = bsm[mm][tx];
            #pragma unroll
            for (int i = 0; i < 4; ++i) acc[i] = fmaf(a[ty+8*i][mm], bv, acc[i]);
        }
        __syncthreads();
    }
    #pragma unroll
    for (int i = 0; i < 4; ++i){
        const int k = c0 + ty + 8*i, n = p0 + tx;
        __nv_bfloat16 h = __float2bfloat16(acc[i]);
        out[cidx(16, 0, 0, n, k)] = h;
        out[cidx(16, 1, 0, n, k)] = __float2bfloat16(acc[i] - __bfloat162float(h));
    }
}

// folded bias
__global__ void bfold(const float* __restrict__ bq, const float* __restrict__ bk,
                      const float* __restrict__ bf, const float* __restrict__ Wf,
                      float* __restrict__ obq, float* __restrict__ obk)
{
    const int which = blockIdx.x & 1, l = blockIdx.x >> 1;
    const float* bb  = (which ? bk : bq) + l*Dd;
    const float* Wfl = Wf + (long)l*Dd*Pp;
    const int p = threadIdx.x, ty = threadIdx.y;   // block (128, 8)
    float s = 0.f;
    #pragma unroll 8
    for (int c = ty; c < Dd; c += 8)
        s = fmaf(bb[c], Wfl[(long)c*Pp + p], s);
    __shared__ float sh[8][128];
    sh[ty][p] = s;
    __syncthreads();
    if (ty == 0){
        float t = bf[l*Pp + p];
        #pragma unroll
        for (int i = 0; i < 8; i++) t += sh[i][p];
        (which ? obk : obq)[l*Pp + p] = t;
    }
}

// ksum[b,p] = sum_s pkT(hi+lo)
__global__ void ksum_kernel(const __nv_bfloat16* __restrict__ pkT, float* __restrict__ ks)
{
    const int p = blockIdx.x, b = blockIdx.y, t = threadIdx.x;
    const __nv_bfloat16* base = pkT + (long)b*2*Pp*Ss;
    float s = 0.f;
    for (int o = t; o < 512; o += 256){
        #pragma unroll
        for (int pl = 0; pl < 2; ++pl){
            long e = (((long)(pl*(Ss>>5)) + (o>>2)) << 12) + (((o&3)*128 + p) << 3);
            uint4 v = *(const uint4*)(base + e);
            const __nv_bfloat162* pv = (const __nv_bfloat162*)&v;
            #pragma unroll
            for (int q = 0; q < 4; ++q)
                s += __bfloat162float(pv[q].x) + __bfloat162float(pv[q].y);
        }
    }
    __shared__ float sh[256];
    sh[t] = s; __syncthreads();
    #pragma unroll
    for (int o = 128; o > 0; o >>= 1){
        if (t < o) sh[t] += sh[t+o];
        __syncthreads();
    }
    if (!t) ks[b*Pp + p] = sh[0];
}

// z[b,s] = dot(pq(hi+lo), ksum)
__global__ void z_kernel(const __nv_bfloat16* __restrict__ pq, const float* __restrict__ ksum,
                         float* __restrict__ z)
{
    int gw = (int)((blockIdx.x*(long)blockDim.x + threadIdx.x) >> 5);
    int lane = threadIdx.x & 31;
    if (gw >= BS) return;
    const int b = gw >> 12, blk = gw >> 7, r = gw & 127;
    const float* kr = ksum + b*Pp;
    const int p0 = lane*4;
    float s = 0.f;
    #pragma unroll
    for (int pl = 0; pl < 2; ++pl){
        long e = (((long)(blk*2+pl)*4 + (p0>>5)) << 12) + ((((p0>>3)&3)*128 + r) << 3) + (p0&7);
        uint2 v = *(const uint2*)(pq + e);
        const __nv_bfloat162* pv = (const __nv_bfloat162*)&v;
        s = fmaf(__bfloat162float(pv[0].x), kr[p0],   s);
        s = fmaf(__bfloat162float(pv[0].y), kr[p0+1], s);
        s = fmaf(__bfloat162float(pv[1].x), kr[p0+2], s);
        s = fmaf(__bfloat162float(pv[1].y), kr[p0+3], s);
    }
    #pragma unroll
    for (int o = 16; o; o >>= 1) s += __shfl_xor_sync(0xffffffffu, s, o);
    if (!lane) z[gw] = s;
}

// layernorm on chunked split data
__global__ void ln_kernel(const __nv_bfloat16* __restrict__ in, const float* __restrict__ g,
                          const float* __restrict__ bta, __nv_bfloat16* __restrict__ out)
{
    const int row = blockIdx.x, t = threadIdx.x;
    const int blk = row >> 7, r = row & 127, d = 2*t;
    const long eh = cidx(16, 0, blk, r, d);
    const long el = cidx(16, 1, blk, r, d);
    __nv_bfloat162 h2 = *(const __nv_bfloat162*)(in + eh);
    __nv_bfloat162 l2 = *(const __nv_bfloat162*)(in + el);
    float vx = __bfloat162float(h2.x) + __bfloat162float(l2.x);
    float vy = __bfloat162float(h2.y) + __bfloat162float(l2.y);
    float s  = vx + vy, sq = vx*vx + vy*vy;
    #pragma unroll
    for (int o = 16; o; o >>= 1){
        s  += __shfl_xor_sync(0xffffffffu, s,  o);
        sq += __shfl_xor_sync(0xffffffffu, sq, o);
    }
    __shared__ float sh[8], shq[8];
    int w = t >> 5, lane = t & 31;
    if (!lane){ sh[w] = s; shq[w] = sq; }
    __syncthreads();
    float ts = 0.f, tq = 0.f;
    #pragma unroll
    for (int i = 0; i < 8; i++){ ts += sh[i]; tq += shq[i]; }
    float mu = ts*(1.f/Dd);
    float rv = rsqrtf(tq*(1.f/Dd) - mu*mu + 1e-5f);
    float ox = (vx-mu)*rv*g[d]   + bta[d];
    float oy = (vy-mu)*rv*g[d+1] + bta[d+1];
    __nv_bfloat16 hx = __float2bfloat16(ox), hy = __float2bfloat16(oy);
    __nv_bfloat162 oh; oh.x = hx; oh.y = hy;
    __nv_bfloat162 ol;
    ol.x = __float2bfloat16(ox - __bfloat162float(hx));
    ol.y = __float2bfloat16(oy - __bfloat162float(hy));
    *(__nv_bfloat162*)(out + eh) = oh;
    *(__nv_bfloat162*)(out + el) = ol;
}

__global__ void embed_kernel(const int* __restrict__ x, const float* __restrict__ emb,
                             const float* __restrict__ pos, __nv_bfloat16* __restrict__ h)
{
    const int token = blockIdx.x, t = threadIdx.x;
    const int s = token & (Ss-1), id = x[token];
    const int blk = token >> 7, r = token & 127, d = 2*t;
    float2 e = *(const float2*)(emb + (long)id*Dd + d);
    float2 p = *(const float2*)(pos + (long)s*Dd + d);
    float vx = e.x + p.x, vy = e.y + p.y;
    __nv_bfloat16 hx = __float2bfloat16(vx), hy = __float2bfloat16(vy);
    __nv_bfloat162 oh; oh.x = hx; oh.y = hy;
    __nv_bfloat162 ol;
    ol.x = __float2bfloat16(vx - __bfloat162float(hx));
    ol.y = __float2bfloat16(vy - __bfloat162float(hy));
    *(__nv_bfloat162*)(h + cidx(16, 0, blk, r, d)) = oh;
    *(__nv_bfloat162*)(h + cidx(16, 1, blk, r, d)) = ol;
}

// partial col sums of hS (chunked) for mean pool
__global__ void colsum_part(const __nv_bfloat16* __restrict__ in, float* __restrict__ part)
{
    const int b = blockIdx.y, ch = blockIdx.x, c = threadIdx.x;
    const int blkg = b*32 + ch;
    float s = 0.f;
    #pragma unroll
    for (int pl = 0; pl < 2; ++pl){
        long base = (((long)(blkg*2+pl)*16 + (c>>5)) << 12) + (((c>>3)&3)*128 << 3) + (c&7);
        #pragma unroll 4
        for (int i = 0; i < 128; ++i)
            s += __bfloat162float(in[base + i*8]);
    }
    part[((long)b*32 + ch)*Dd + c] = s;
}
__global__ void colsum_fin(const float* __restrict__ part, float* __restrict__ out,
                           int cols, int chunks, float scale)
{
    int b = blockIdx.x, c = threadIdx.x;
    float s = 0.f;
    for (int ch = 0; ch < chunks; ch++) s += part[((long)b*chunks+ch)*cols + c];
    out[(long)b*cols + c] = s*scale;
}

__global__ void head1_kernel(const float* __restrict__ pool, const float* __restrict__ Wh1,
                             const float* __restrict__ bh1, float* __restrict__ h1)
{
    int b = blockIdx.x;
    __shared__ float xr[Dd];
    for (int i = threadIdx.x; i < Dd; i += blockDim.x) xr[i] = pool[(long)b*Dd + i];
    __syncthreads();
    int t = threadIdx.x;
    float s = bh1[t];
    #pragma unroll 4
    for (int k = 0; k < Dd; k++) s = fmaf(xr[k], Wh1[(long)k*DHh + t], s);
    h1[(long)b*DHh + t] = fmaxf(s, 0.f);
}
__global__ void head2_kernel(const float* __restrict__ h1, const float* __restrict__ Wh2,
                             const float* __restrict__ bh2, float* __restrict__ out)
{
    int t = threadIdx.x;
    if (t < Bb*CC){
        int b = t / CC, c = t % CC;
        float s = bh2[c];
        #pragma unroll 4
        for (int k = 0; k < DHh; k++) s = fmaf(h1[(long)b*DHh + k], Wh2[(long)k*CC + c], s);
        out[t] = s;
    }
}

// ===================== launch =====================
extern "C" void kernel_launch(void* const* d_in, const int* in_sizes, int n_in,
                              void* d_out, int out_size)
{
    const int*   x   = (const int*)  d_in[0];
    const float* emb = (const float*)d_in[1];
    const float* pos = (const float*)d_in[2];
    const float* Wq  = (const float*)d_in[3];   const float* bq = (const float*)d_in[4];
    const float* Wk  = (const float*)d_in[5];   const float* bk = (const float*)d_in[6];
    const float* Wv  = (const float*)d_in[7];   const float* bv = (const float*)d_in[8];
    const float* Wf  = (const float*)d_in[9];   const float* bf = (const float*)d_in[10];
    const float* Wo  = (const float*)d_in[11];  const float* bo = (const float*)d_in[12];
    const float* lng = (const float*)d_in[13];  const float* lnb= (const float*)d_in[14];
    const float* W1  = (const float*)d_in[15];  const float* b1 = (const float*)d_in[16];
    const float* W2  = (const float*)d_in[17];  const float* b2 = (const float*)d_in[18];
    const float* Wh1 = (const float*)d_in[19];  const float* bh1= (const float*)d_in[20];
    const float* Wh2 = (const float*)d_in[21];  const float* bh2= (const float*)d_in[22];

    __nv_bfloat16 *hS,*qS,*vT,*tS,*pqS,*pkT,*mS,*kvtS,*wv,*wo,*w1,*w2,*wqf,*wkf;
    float *bqf,*bkf,*kvp,*ks,*z,*pp,*pool,*h1;
    cudaGetSymbolAddress((void**)&hS,  g_hS);   cudaGetSymbolAddress((void**)&qS,  g_qS);
    cudaGetSymbolAddress((void**)&vT,  g_vT);   cudaGetSymbolAddress((void**)&tS,  g_tS);
    cudaGetSymbolAddress((void**)&pqS, g_pqS);  cudaGetSymbolAddress((void**)&pkT, g_pkT);
    cudaGetSymbolAddress((void**)&mS,  g_mS);   cudaGetSymbolAddress((void**)&kvtS,g_kvtS);
    cudaGetSymbolAddress((void**)&wv, g_wv); cudaGetSymbolAddress((void**)&wo, g_wo);
    cudaGetSymbolAddress((void**)&w1, g_w1); cudaGetSymbolAddress((void**)&w2, g_w2);
    cudaGetSymbolAddress((void**)&wqf, g_wqf); cudaGetSymbolAddress((void**)&wkf, g_wkf);
    cudaGetSymbolAddress((void**)&bqf, g_bqf); cudaGetSymbolAddress((void**)&bkf, g_bkf);
    cudaGetSymbolAddress((void**)&kvp, g_kvp);
    cudaGetSymbolAddress((void**)&ks,  g_ks);  cudaGetSymbolAddress((void**)&z,   g_z);
    cudaGetSymbolAddress((void**)&pp,  g_pp);  cudaGetSymbolAddress((void**)&pool,g_pool);
    cudaGetSymbolAddress((void**)&h1,  g_h1);

    const int SMEM3 = 1024 + NSTG*65536;
    cudaFuncSetAttribute(gemm_mma<0,0,3>, cudaFuncAttributeMaxDynamicSharedMemorySize, SMEM3);
    cudaFuncSetAttribute(gemm_mma<0,1,3>, cudaFuncAttributeMaxDynamicSharedMemorySize, SMEM3);
    cudaFuncSetAttribute(gemm_mma<1,0,3>, cudaFuncAttributeMaxDynamicSharedMemorySize, SMEM3);
    cudaFuncSetAttribute(gemm_mma<1,1,3>, cudaFuncAttributeMaxDynamicSharedMemorySize, SMEM3);
    cudaFuncSetAttribute(gemm_mma<3,0,3>, cudaFuncAttributeMaxDynamicSharedMemorySize, SMEM3);
    cudaFuncSetAttribute(gemm_mma<2,0,3>, cudaFuncAttributeMaxDynamicSharedMemorySize, SMEM3);
    cudaFuncSetAttribute(gemm_kv,         cudaFuncAttributeMaxDynamicSharedMemorySize, SMEM3);

    dim3 wt(32, 8);
    const dim3 gDD(Dd/128, BS/128, 1);
    const dim3 gDP(1,      BS/128, 1);
    const dim3 gDF(DFf/128,BS/128, 1);
    const dim3 gAT(Dd/128, Ss/128, Bb);
    const dim3 gKV(1, Dd/128, Bb*KVS);
    const long wDD = (long)2*Dd*Dd, wPD = (long)2*Pp*Dd, wDF = (long)2*DFf*Dd;

    // launch order: gemm_mma V (l=0) at launch index 3 so ncu captures a GEMM
    embed_kernel<<<BS,256>>>(x, emb, pos, hS);                          // 0
    wconv<<<dim3(Dd/32, Dd/32, Ll), wt>>>(Wv, wv, Dd, Dd);              // 1
    wfold<<<dim3(Pp/32, Dd/32, 2*Ll), wt>>>(Wq, Wk, Wf, wqf, wkf);      // 2
    gemm_mma<0,1,3><<<gDD,256,SMEM3>>>(hS, 16, wv, 16, 0, bv, nullptr, vT, Dd, Dd);  // 3 (l=0 V)
    bfold<<<2*Ll, dim3(128,8)>>>(bq, bk, bf, Wf, bqf, bkf);             // 4
    wconv<<<dim3(Dd/32, Dd/32, Ll), wt>>>(Wo, wo, Dd, Dd);              // 5
    wconv<<<dim3(DFf/32, Dd/32,  Ll), wt>>>(W1, w1, Dd, DFf);           // 6
    wconv<<<dim3(Dd/32,  DFf/32, Ll), wt>>>(W2, w2, DFf, Dd);           // 7

    for (int l = 0; l < Ll; l++){
        if (l > 0)
            gemm_mma<0,1,3><<<gDD,256,SMEM3>>>(hS, 16, wv + l*wDD, 16, 0, bv + l*Dd, nullptr, vT, Dd, Dd);
        gemm_mma<1,0,3><<<gDP,256,SMEM3>>>(hS, 16, wqf + l*wPD, 16, 0, bqf + l*Pp, nullptr, pqS, Pp, Dd);
        gemm_mma<1,1,3><<<gDP,256,SMEM3>>>(hS, 16, wkf + l*wPD, 16, 0, bkf + l*Pp, nullptr, pkT, Pp, Dd);
        ksum_kernel<<<dim3(Pp,Bb),256>>>(pkT, ks);
        gemm_kv<<<gKV,256,SMEM3>>>(vT, pkT, kvp);
        reduce_kvt<<<(Bb*Dd*Pp)/256,256>>>(kvp, kvtS);
        z_kernel<<<BS/8,256>>>(pqS, ks, z);
        gemm_mma<3,0,3><<<gAT,256,SMEM3>>>(pqS, 4, kvtS, 4, (long)2*Dd*Pp, nullptr, z, tS, Dd, Pp);
        gemm_mma<0,0,3><<<gDD,256,SMEM3>>>(tS, 16, wo + l*wDD, 16, 0, bo + l*Dd, nullptr, qS, Dd, Dd);
        ln_kernel<<<BS,256>>>(qS, lng + l*Dd, lnb + l*Dd, tS);
        gemm_mma<2,0,3><<<gDF,256,SMEM3>>>(tS, 16, w1 + l*wDF, 16, 0, b1 + l*DFf, nullptr, mS, DFf, Dd);
        gemm_mma<0,0,3><<<gDD,256,SMEM3>>>(mS, 64, w2 + l*wDF, 64, 0, b2 + l*Dd, nullptr, hS, Dd, DFf);
    }

    colsum_part<<<dim3(32,Bb),Dd>>>(hS, pp);
    colsum_fin <<<Bb,Dd>>>(pp, pool, Dd, 32, 1.0f/Ss);
    head1_kernel<<<Bb,DHh>>>(pool, Wh1, bh1, h1);
    head2_kernel<<<1,32>>>(h1, Wh2, bh2, (float*)d_out);
}

// round 14
// speedup vs baseline: 1.1202x; 1.1202x over previous
#include <cuda_runtime.h>
#include <cuda_bf16.h>
#include <math.h>
#include <stdint.h>

#define Bb  8
#define Ss  4096
#define Dd  512
#define Pp  128
#define Ll  4
#define DFf 2048
#define DHh 256
#define CC  2
#define BS  (Bb*Ss)
#define KVS 8

// ===================== PTX helpers (sm_90 core features only) =====================
__device__ __forceinline__ uint32_t smem_to_u32(const void* p) {
    uint32_t a;
    asm("{ .reg .u64 t; cvta.to.shared.u64 t, %1; cvt.u32.u64 %0, t; }" : "=r"(a) : "l"(p));
    return a;
}
#define MBARRIER_INIT(m, c) \
    asm volatile("mbarrier.init.shared.b64 [%0], %1;" :: "r"((uint32_t)(m)), "r"((uint32_t)(c)) : "memory")
#define MBARRIER_EXPECT_TX(m, b) \
    asm volatile("mbarrier.arrive.expect_tx.shared.b64 _, [%0], %1;" :: "r"((uint32_t)(m)), "r"((uint32_t)(b)) : "memory")
#define MBARRIER_ARRIVE(m) \
    asm volatile("mbarrier.arrive.shared.b64 _, [%0];" :: "r"((uint32_t)(m)) : "memory")
#define MBARRIER_WAIT_PARITY(m, par) do { \
    uint32_t _m=(uint32_t)(m), _p=(uint32_t)(par), _d; \
    asm volatile("{\n\t.reg .pred p;\n\tmbarrier.try_wait.parity.acquire.cta.shared::cta.b64 p, [%1], %2;\n\tselp.b32 %0,1,0,p;\n\t}" \
        : "=r"(_d) : "r"(_m), "r"(_p) : "memory"); \
    if (!_d) { \
        asm volatile("{\n\t.reg .pred P1;\n\tWL_%=:\n\tmbarrier.try_wait.parity.acquire.cta.shared::cta.b64 P1, [%0], %1, 0x989680;\n\t@P1 bra.uni WD_%=;\n\tbra.uni WL_%=;\n\tWD_%=:\n\t}" \
            :: "r"(_m), "r"(_p) : "memory"); \
    } \
} while(0)
__device__ __forceinline__ void bulk_g2s(uint32_t dst, const void* src, uint32_t bytes, uint32_t mbar){
    asm volatile("cp.async.bulk.shared::cluster.global.mbarrier::complete_tx::bytes [%0], [%1], %2, [%3];"
        :: "r"(dst), "l"(src), "r"(bytes), "r"(mbar) : "memory");
}
__device__ __forceinline__ void ldsm4(uint32_t* r, uint32_t addr){
    asm volatile("ldmatrix.sync.aligned.m8n8.x4.shared.b16 {%0,%1,%2,%3}, [%4];"
        : "=r"(r[0]),"=r"(r[1]),"=r"(r[2]),"=r"(r[3]) : "r"(addr));
}
__device__ __forceinline__ void mma_bf16(float* d, const uint32_t* a, const uint32_t* b){
    asm volatile("mma.sync.aligned.m16n8k16.row.col.f32.bf16.bf16.f32 "
        "{%0,%1,%2,%3}, {%4,%5,%6,%7}, {%8,%9}, {%0,%1,%2,%3};"
        : "+f"(d[0]),"+f"(d[1]),"+f"(d[2]),"+f"(d[3])
        : "r"(a[0]),"r"(a[1]),"r"(a[2]),"r"(a[3]), "r"(b[0]),"r"(b[1]));
}

// ===================== chunk-packed layout =====================
__device__ __forceinline__ long cidx(int KC, int pl, int blk, int r, int k){
    return (((long)(blk*2 + pl)*KC + (k>>5)) << 12) + ((((k>>3)&3)*128 + r) << 3) + (k&7);
}

// ===================== device globals =====================
__device__ __align__(256) __nv_bfloat16 g_hS [2*(size_t)BS*Dd];
__device__ __align__(256) __nv_bfloat16 g_qS [2*(size_t)BS*Dd];
__device__ __align__(256) __nv_bfloat16 g_vT [2*(size_t)BS*Dd];
__device__ __align__(256) __nv_bfloat16 g_tS [2*(size_t)BS*Dd];
__device__ __align__(256) __nv_bfloat16 g_pqS[2*(size_t)BS*Pp];
__device__ __align__(256) __nv_bfloat16 g_pkT[2*(size_t)BS*Pp];
__device__ __align__(256) __nv_bfloat16 g_mS [2*(size_t)BS*DFf];
__device__ __align__(256) __nv_bfloat16 g_kvtS[(size_t)Bb*2*Dd*Pp];
__device__ __align__(256) __nv_bfloat16 g_wv[(size_t)Ll*2*Dd*Dd];
__device__ __align__(256) __nv_bfloat16 g_wo[(size_t)Ll*2*Dd*Dd];
__device__ __align__(256) __nv_bfloat16 g_w1[(size_t)Ll*2*DFf*Dd];
__device__ __align__(256) __nv_bfloat16 g_w2[(size_t)Ll*2*Dd*DFf];
__device__ __align__(256) __nv_bfloat16 g_wqf[(size_t)Ll*2*Pp*Dd];
__device__ __align__(256) __nv_bfloat16 g_wkf[(size_t)Ll*2*Pp*Dd];
__device__ float g_bqf[Ll*Pp];
__device__ float g_bkf[Ll*Pp];
__device__ float g_kvp[(size_t)Bb*KVS*Pp*Dd];
__device__ float g_ks [Bb*Pp];
__device__ float g_z  [BS];
__device__ float g_pp [Bb*32*Dd];
__device__ float g_pool[Bb*Dd];
__device__ float g_h1 [Bb*DHh];

__device__ __forceinline__ float gelu_tanh(float x){
    float u = 0.7978845608028654f*(x + 0.044715f*x*x*x);
    return 0.5f*x*(1.0f + tanhf(u));
}

// ===================== bulk-pipelined split-bf16 HMMA GEMM =====================
// K=32 stages: [Ah 8K][Al 8K][Bh 8K][Bl 8K] = 32KB; NSTG=3 -> 97KB smem -> 2 CTAs/SM.
#define NSTG 3
#define STGB 32768
#define SMEMG (1024 + NSTG*STGB)

// EPI 0:+bias 1:+bias,elu+1 2:+bias,gelu 3:*1/(aux+eps)
// TOUT 0:chunked [M,N], 1:transposed chunked [N rows][Ss]
template<int EPI, int TOUT>
__global__ void __launch_bounds__(256, 2)
gemm_mma(const __nv_bfloat16* __restrict__ A, int KCa,
         const __nv_bfloat16* __restrict__ Bw, int KCb, long b_batch,
         const float* __restrict__ bias, const float* __restrict__ aux,
         __nv_bfloat16* __restrict__ C, int N, int K)
{
    extern __shared__ __align__(1024) char smem[];
    const uint32_t sb = smem_to_u32(smem);
    const int tid = threadIdx.x, wid = tid >> 5, lane = tid & 31;
    const int rowblk = blockIdx.z*gridDim.y + blockIdx.y;
    const int nblk = blockIdx.x;
    const int row0 = rowblk*128, col0 = nblk*128;
    const int niter = K >> 5;
    const uint32_t FULL0 = sb, EMPTY0 = sb + 32;
    const uint32_t STG0 = sb + 1024;
    const __nv_bfloat16* Bt = Bw + (long)blockIdx.z*b_batch;

    if (tid == 0){
        #pragma unroll
        for (int s = 0; s < NSTG; ++s){ MBARRIER_INIT(FULL0+8*s, 1); MBARRIER_INIT(EMPTY0+8*s, 256); }
    }
    __syncthreads();

    auto issue = [&](int j){
        const int s = j % NSTG;
        if (j >= NSTG) MBARRIER_WAIT_PARITY(EMPTY0+8*s, ((j/NSTG)-1)&1);
        MBARRIER_EXPECT_TX(FULL0+8*s, 32768u);
        const uint32_t dst = STG0 + s*STGB;
        bulk_g2s(dst,         A  + (((long)(rowblk*2  )*KCa + j) << 12), 8192u, FULL0+8*s);
        bulk_g2s(dst + 8192,  A  + (((long)(rowblk*2+1)*KCa + j) << 12), 8192u, FULL0+8*s);
        bulk_g2s(dst + 16384, Bt + (((long)(nblk*2  )*KCb + j) << 12), 8192u, FULL0+8*s);
        bulk_g2s(dst + 24576, Bt + (((long)(nblk*2+1)*KCb + j) << 12), 8192u, FULL0+8*s);
    };
    if (tid == 0){
        const int pro = (niter < NSTG-1) ? niter : NSTG-1;
        for (int j = 0; j < pro; ++j) issue(j);
    }

    float acc[2][8][4];
    #pragma unroll
    for (int mt=0;mt<2;mt++)
        #pragma unroll
        for (int ni=0;ni<8;ni++)
            #pragma unroll
            for (int r=0;r<4;r++) acc[mt][ni][r]=0.f;

    const int wm = (wid >> 1)*32, wn = (wid & 1)*64;
    const int a_mrow = wm + ((lane>>3)&1)*8 + (lane&7);
    const int a_kc   = (lane>>4);
    const int b_nrow = wn + ((lane>>4)&1)*8 + (lane&7);
    const int b_kc   = ((lane>>3)&1);

    for (int it = 0; it < niter; ++it){
        const int s = it % NSTG;
        if (tid == 0 && it + NSTG-1 < niter) issue(it + NSTG-1);
        MBARRIER_WAIT_PARITY(FULL0+8*s, (it/NSTG)&1);
        const uint32_t stg = STG0 + s*STGB;
        #pragma unroll
        for (int step = 0; step < 2; ++step){
            const int ga = a_kc + 2*step, gb = b_kc + 2*step;
            uint32_t ah[2][4], al[2][4];
            #pragma unroll
            for (int mt = 0; mt < 2; ++mt){
                const uint32_t aoff = stg + (uint32_t)(((ga*128) + a_mrow + mt*16)*16);
                ldsm4(ah[mt], aoff);
                ldsm4(al[mt], aoff + 8192);
            }
            #pragma unroll
            for (int nt4 = 0; nt4 < 4; ++nt4){
                const uint32_t boff = stg + 16384 + (uint32_t)(((gb*128) + b_nrow + nt4*16)*16);
                uint32_t bh[4], bl[4];
                ldsm4(bh, boff);
                ldsm4(bl, boff + 8192);
                #pragma unroll
                for (int mt = 0; mt < 2; ++mt){
                    mma_bf16(acc[mt][2*nt4  ], ah[mt], bh);
                    mma_bf16(acc[mt][2*nt4+1], ah[mt], bh+2);
                    mma_bf16(acc[mt][2*nt4  ], al[mt], bh);
                    mma_bf16(acc[mt][2*nt4+1], al[mt], bh+2);
                    mma_bf16(acc[mt][2*nt4  ], ah[mt], bl);
                    mma_bf16(acc[mt][2*nt4+1], ah[mt], bl+2);
                }
            }
        }
        MBARRIER_ARRIVE(EMPTY0+8*s);
    }

    // ---- epilogue ----
    float bv0[8], bv1[8];
    if (EPI != 3){
        #pragma unroll
        for (int ni = 0; ni < 8; ++ni){
            const int col = col0 + wn + ni*8 + (lane&3)*2;
            bv0[ni] = bias[col]; bv1[ni] = bias[col+1];
        }
    }

    if (TOUT == 0){
        const int KCo = N >> 5;
        #pragma unroll
        for (int mt = 0; mt < 2; ++mt){
            #pragma unroll
            for (int h = 0; h < 2; ++h){
                const long row = row0 + wm + mt*16 + h*8 + (lane>>2);
                float sc = 1.f;
                if (EPI == 3) sc = 1.f/(aux[row] + 1e-6f);
                const int r = (int)(row & 127);
                #pragma unroll
                for (int ni = 0; ni < 8; ++ni){
                    const int col = col0 + wn + ni*8 + (lane&3)*2;
                    float c0 = acc[mt][ni][2*h], c1 = acc[mt][ni][2*h+1];
                    if (EPI != 3){ c0 += bv0[ni]; c1 += bv1[ni]; }
                    if (EPI == 1){ c0 = (c0>0.f)?(c0+1.f):expf(c0); c1 = (c1>0.f)?(c1+1.f):expf(c1); }
                    if (EPI == 2){ c0 = gelu_tanh(c0); c1 = gelu_tanh(c1); }
                    if (EPI == 3){ c0 *= sc; c1 *= sc; }
                    __nv_bfloat16 h0 = __float2bfloat16(c0), h1 = __float2bfloat16(c1);
                    __nv_bfloat162 vh; vh.x = h0; vh.y = h1;
                    __nv_bfloat162 vl;
                    vl.x = __float2bfloat16(c0 - __bfloat162float(h0));
                    vl.y = __float2bfloat16(c1 - __bfloat162float(h1));
                    *(__nv_bfloat162*)(C + cidx(KCo, 0, rowblk, r, col)) = vh;
                    *(__nv_bfloat162*)(C + cidx(KCo, 1, rowblk, r, col)) = vl;
                }
            }
        }
    } else {
        #pragma unroll
        for (int mt = 0; mt < 2; ++mt)
            #pragma unroll
            for (int ni = 0; ni < 8; ++ni){
                #pragma unroll
                for (int h = 0; h < 2; ++h){
                    float c0 = acc[mt][ni][2*h] + bv0[ni];
                    float c1 = acc[mt][ni][2*h+1] + bv1[ni];
                    if (EPI == 1){ c0 = (c0>0.f)?(c0+1.f):expf(c0); c1 = (c1>0.f)?(c1+1.f):expf(c1); }
                    acc[mt][ni][2*h] = c0; acc[mt][ni][2*h+1] = c1;
                }
            }
        __syncthreads();
        __nv_bfloat16* sT = (__nv_bfloat16*)(smem + 1024);   // [128 col][136 tok] = 34816B
        const int st0 = (int)(row0 & (Ss-1));
        const int cb = col0 >> 7;
        const int KCss = Ss >> 5;
        __nv_bfloat16* tB = C + (long)(row0 >> 12)*2*(long)N*Ss;
        #pragma unroll
        for (int pl = 0; pl < 2; ++pl){
            #pragma unroll
            for (int mt = 0; mt < 2; ++mt){
                #pragma unroll
                for (int h = 0; h < 2; ++h){
                    const int tok = wm + mt*16 + h*8 + (lane>>2);
                    #pragma unroll
                    for (int ni = 0; ni < 8; ++ni){
                        const int col = wn + ni*8 + (lane&3)*2;
                        float c0 = acc[mt][ni][2*h], c1 = acc[mt][ni][2*h+1];
                        __nv_bfloat16 h0 = __float2bfloat16(c0), h1 = __float2bfloat16(c1);
                        if (pl){
                            h0 = __float2bfloat16(c0 - __bfloat162float(h0));
                            h1 = __float2bfloat16(c1 - __bfloat162float(h1));
                        }
                        sT[col*136 + tok]     = h0;
                        sT[(col+1)*136 + tok] = h1;
                    }
                }
            }
            __syncthreads();
            #pragma unroll
            for (int j = 0; j < 8; ++j){
                const int idx = j*256 + tid;
                const int oct = idx >> 7, n = idx & 127;
                uint4 v = *(const uint4*)(sT + n*136 + oct*8);
                const int st = st0 + oct*8;
                long e = (((long)(cb*2+pl)*KCss + (st>>5)) << 12) + ((((st>>3)&3)*128 + n) << 3);
                *(uint4*)(tB + e) = v;
            }
            __syncthreads();
        }
    }
}

// ===================== kv gemm: kv^T[b] = vT[b] @ pkT[b]^T, split-K fp32 partials =====================
__global__ void __launch_bounds__(256, 2)
gemm_kv(const __nv_bfloat16* __restrict__ vT, const __nv_bfloat16* __restrict__ pkT,
        float* __restrict__ part)
{
    extern __shared__ __align__(1024) char smem[];
    const uint32_t sb = smem_to_u32(smem);
    const int tid = threadIdx.x, wid = tid >> 5, lane = tid & 31;
    const int bz = blockIdx.z, b = bz >> 3, sp = bz & (KVS-1);
    const int ablk = blockIdx.y, row0 = ablk*128;
    const int niter = (Ss/KVS) >> 5;      // 16
    const int kchunk0 = sp*((Ss/KVS) >> 5);
    const uint32_t FULL0 = sb, EMPTY0 = sb + 32;
    const uint32_t STG0 = sb + 1024;
    const __nv_bfloat16* A  = vT  + (long)b*2*Dd*Ss;
    const __nv_bfloat16* Bp = pkT + (long)b*2*Pp*Ss;

    if (tid == 0){
        #pragma unroll
        for (int s = 0; s < NSTG; ++s){ MBARRIER_INIT(FULL0+8*s, 1); MBARRIER_INIT(EMPTY0+8*s, 256); }
    }
    __syncthreads();

    auto issue = [&](int j){
        const int s = j % NSTG;
        if (j >= NSTG) MBARRIER_WAIT_PARITY(EMPTY0+8*s, ((j/NSTG)-1)&1);
        MBARRIER_EXPECT_TX(FULL0+8*s, 32768u);
        const uint32_t dst = STG0 + s*STGB;
        bulk_g2s(dst,         A  + (((long)(ablk*2  )*(Ss>>5) + kchunk0 + j) << 12), 8192u, FULL0+8*s);
        bulk_g2s(dst + 8192,  A  + (((long)(ablk*2+1)*(Ss>>5) + kchunk0 + j) << 12), 8192u, FULL0+8*s);
        bulk_g2s(dst + 16384, Bp + (((long)(0      )*(Ss>>5) + kchunk0 + j) << 12), 8192u, FULL0+8*s);
        bulk_g2s(dst + 24576, Bp + (((long)(1      )*(Ss>>5) + kchunk0 + j) << 12), 8192u, FULL0+8*s);
    };
    if (tid == 0){ for (int j = 0; j < NSTG-1; ++j) issue(j); }

    float acc[2][8][4];
    #pragma unroll
    for (int mt=0;mt<2;mt++)
        #pragma unroll
        for (int ni=0;ni<8;ni++)
            #pragma unroll
            for (int r=0;r<4;r++) acc[mt][ni][r]=0.f;

    const int wm = (wid >> 1)*32, wn = (wid & 1)*64;
    const int a_mrow = wm + ((lane>>3)&1)*8 + (lane&7);
    const int a_kc   = (lane>>4);
    const int b_nrow = wn + ((lane>>4)&1)*8 + (lane&7);
    const int b_kc   = ((lane>>3)&1);

    for (int it = 0; it < niter; ++it){
        const int s = it % NSTG;
        if (tid == 0 && it + NSTG-1 < niter) issue(it + NSTG-1);
        MBARRIER_WAIT_PARITY(FULL0+8*s, (it/NSTG)&1);
        const uint32_t stg = STG0 + s*STGB;
        #pragma unroll
        for (int step = 0; step < 2; ++step){
            const int ga = a_kc + 2*step, gb = b_kc + 2*step;
            uint32_t ah[2][4], al[2][4];
            #pragma unroll
            for (int mt = 0; mt < 2; ++mt){
                const uint32_t aoff = stg + (uint32_t)(((ga*128) + a_mrow + mt*16)*16);
                ldsm4(ah[mt], aoff);
                ldsm4(al[mt], aoff + 8192);
            }
            #pragma unroll
            for (int nt4 = 0; nt4 < 4; ++nt4){
                const uint32_t boff = stg + 16384 + (uint32_t)(((gb*128) + b_nrow + nt4*16)*16);
                uint32_t bh[4], bl[4];
                ldsm4(bh, boff);
                ldsm4(bl, boff + 8192);
                #pragma unroll
                for (int mt = 0; mt < 2; ++mt){
                    mma_bf16(acc[mt][2*nt4  ], ah[mt], bh);
                    mma_bf16(acc[mt][2*nt4+1], ah[mt], bh+2);
                    mma_bf16(acc[mt][2*nt4  ], al[mt], bh);
                    mma_bf16(acc[mt][2*nt4+1], al[mt], bh+2);
                    mma_bf16(acc[mt][2*nt4  ], ah[mt], bl);
                    mma_bf16(acc[mt][2*nt4+1], ah[mt], bl+2);
                }
            }
        }
        MBARRIER_ARRIVE(EMPTY0+8*s);
    }

    float* Cb = part + (long)bz*Dd*Pp;
    #pragma unroll
    for (int mt = 0; mt < 2; ++mt){
        #pragma unroll
        for (int h = 0; h < 2; ++h){
            const int row = row0 + wm + mt*16 + h*8 + (lane>>2);
            #pragma unroll
            for (int ni = 0; ni < 8; ++ni){
                const int col = wn + ni*8 + (lane&3)*2;
                *(float2*)(Cb + (long)row*Pp + col) =
                    make_float2(acc[mt][ni][2*h], acc[mt][ni][2*h+1]);
            }
        }
    }
}

// reduce partials -> kvtS chunked [D rows][P] per batch
__global__ void reduce_kvt(const float* __restrict__ part, __nv_bfloat16* __restrict__ kvt)
{
    long i = (long)blockIdx.x*256 + threadIdx.x;
    int b = (int)(i / (Dd*Pp)); int r0 = (int)(i % (Dd*Pp));
    int d = r0 >> 7, p = r0 & 127;
    const float* q = part + ((long)b*KVS)*Dd*Pp + r0;
    float s = 0.f;
    #pragma unroll
    for (int j = 0; j < KVS; j++) s += q[(long)j*Dd*Pp];
    __nv_bfloat16 h = __float2bfloat16(s);
    __nv_bfloat16* base = kvt + (long)b*2*Dd*Pp;
    base[cidx(4, 0, d>>7, d&127, p)] = h;
    base[cidx(4, 1, d>>7, d&127, p)] = __float2bfloat16(s - __bfloat162float(h));
}

// ===================== weight conversion =====================
__global__ void wconv(const float* __restrict__ W, __nv_bfloat16* __restrict__ out, int K, int N)
{
    __shared__ float t[32][33];
    const int n0 = blockIdx.x*32, k0 = blockIdx.y*32, l = blockIdx.z;
    const float* Wl = W + (long)l*K*N;
    __nv_bfloat16* ob = out + (long)l*2*N*K;
    const int KC = K >> 5;
    for (int i = threadIdx.y; i < 32; i += 8)
        t[i][threadIdx.x] = Wl[(long)(k0+i)*N + n0 + threadIdx.x];
    __syncthreads();
    for (int i = threadIdx.y; i < 32; i += 8) {
        float v = t[threadIdx.x][i];
        const int n = n0 + i, k = k0 + threadIdx.x;
        __nv_bfloat16 h = __float2bfloat16(v);
        ob[cidx(KC, 0, n>>7, n&127, k)] = h;
        ob[cidx(KC, 1, n>>7, n&127, k)] = __float2bfloat16(v - __bfloat162float(h));
    }
}

// folded feature weights
__global__ void wfold(const float* __restrict__ Wq, const float* __restrict__ Wk,
                      const float* __restrict__ Wf,
                      __nv_bfloat16* __restrict__ oq, __nv_bfloat16* __restrict__ ok)
{
    const int which = blockIdx.z & 1, l = blockIdx.z >> 1;
    const float* Wa  = (which ? Wk : Wq) + (long)l*Dd*Dd;
    const float* Wfl = Wf + (long)l*Dd*Pp;
    __nv_bfloat16* out = (which ? ok : oq) + (long)l*2*Pp*Dd;
    const int p0 = blockIdx.x*32, c0 = blockIdx.y*32;
    __shared__ float a[32][33], bsm[32][33];
    const int tx = threadIdx.x, ty = threadIdx.y;
    float acc[4] = {0.f,0.f,0.f,0.f};
    for (int m0 = 0; m0 < Dd; m0 += 32){
        for (int i = ty; i < 32; i += 8) a[i][tx]   = Wa[(long)(c0+i)*Dd + m0+tx];
        for (int i = ty; i < 32; i += 8) bsm[i][tx] = Wfl[(long)(m0+i)*Pp + p0+tx];
        __syncthreads();
        #pragma unroll
        for (int mm = 0; mm < 32; ++mm){
            float bv = bsm[mm][tx];
            #pragma unroll
            for (int i = 0; i < 4; ++i) acc[i] = fmaf(a[ty+8*i][mm], bv, acc[i]);
        }
        __syncthreads();
    }
    #pragma unroll
    for (int i = 0; i < 4; ++i){
        const int k = c0 + ty + 8*i, n = p0 + tx;
        __nv_bfloat16 h = __float2bfloat16(acc[i]);
        out[cidx(16, 0, 0, n, k)] = h;
        out[cidx(16, 1, 0, n, k)] = __float2bfloat16(acc[i] - __bfloat162float(h));
    }
}

// folded bias
__global__ void bfold(const float* __restrict__ bq, const float* __restrict__ bk,
                      const float* __restrict__ bf, const float* __restrict__ Wf,
                      float* __restrict__ obq, float* __restrict__ obk)
{
    const int which = blockIdx.x & 1, l = blockIdx.x >> 1;
    const float* bb  = (which ? bk : bq) + l*Dd;
    const float* Wfl = Wf + (long)l*Dd*Pp;
    const int p = threadIdx.x, ty = threadIdx.y;   // block (128, 8)
    float s = 0.f;
    #pragma unroll 8
    for (int c = ty; c < Dd; c += 8)
        s = fmaf(bb[c], Wfl[(long)c*Pp + p], s);
    __shared__ float sh[8][128];
    sh[ty][p] = s;
    __syncthreads();
    if (ty == 0){
        float t = bf[l*Pp + p];
        #pragma unroll
        for (int i = 0; i < 8; i++) t += sh[i][p];
        (which ? obk : obq)[l*Pp + p] = t;
    }
}

// ksum[b,p] = sum_s pkT(hi+lo)
__global__ void ksum_kernel(const __nv_bfloat16* __restrict__ pkT, float* __restrict__ ks)
{
    const int p = blockIdx.x, b = blockIdx.y, t = threadIdx.x;
    const __nv_bfloat16* base = pkT + (long)b*2*Pp*Ss;
    float s = 0.f;
    for (int o = t; o < 512; o += 256){
        #pragma unroll
        for (int pl = 0; pl < 2; ++pl){
            long e = (((long)(pl*(Ss>>5)) + (o>>2)) << 12) + (((o&3)*128 + p) << 3);
            uint4 v = *(const uint4*)(base + e);
            const __nv_bfloat162* pv = (const __nv_bfloat162*)&v;
            #pragma unroll
            for (int q = 0; q < 4; ++q)
                s += __bfloat162float(pv[q].x) + __bfloat162float(pv[q].y);
        }
    }
    __shared__ float sh[256];
    sh[t] = s; __syncthreads();
    #pragma unroll
    for (int o = 128; o > 0; o >>= 1){
        if (t < o) sh[t] += sh[t+o];
        __syncthreads();
    }
    if (!t) ks[b*Pp + p] = sh[0];
}

// z[b,s] = dot(pq(hi+lo), ksum)
__global__ void z_kernel(const __nv_bfloat16* __restrict__ pq, const float* __restrict__ ksum,
                         float* __restrict__ z)
{
    int gw = (int)((blockIdx.x*(long)blockDim.x + threadIdx.x) >> 5);
    int lane = threadIdx.x & 31;
    if (gw >= BS) return;
    const int b = gw >> 12, blk = gw >> 7, r = gw & 127;
    const float* kr = ksum + b*Pp;
    const int p0 = lane*4;
    float s = 0.f;
    #pragma unroll
    for (int pl = 0; pl < 2; ++pl){
        long e = (((long)(blk*2+pl)*4 + (p0>>5)) << 12) + ((((p0>>3)&3)*128 + r) << 3) + (p0&7);
        uint2 v = *(const uint2*)(pq + e);
        const __nv_bfloat162* pv = (const __nv_bfloat162*)&v;
        s = fmaf(__bfloat162float(pv[0].x), kr[p0],   s);
        s = fmaf(__bfloat162float(pv[0].y), kr[p0+1], s);
        s = fmaf(__bfloat162float(pv[1].x), kr[p0+2], s);
        s = fmaf(__bfloat162float(pv[1].y), kr[p0+3], s);
    }
    #pragma unroll
    for (int o = 16; o; o >>= 1) s += __shfl_xor_sync(0xffffffffu, s, o);
    if (!lane) z[gw] = s;
}

// layernorm on chunked split data
__global__ void ln_kernel(const __nv_bfloat16* __restrict__ in, const float* __restrict__ g,
                          const float* __restrict__ bta, __nv_bfloat16* __restrict__ out)
{
    const int row = blockIdx.x, t = threadIdx.x;
    const int blk = row >> 7, r = row & 127, d = 2*t;
    const long eh = cidx(16, 0, blk, r, d);
    const long el = cidx(16, 1, blk, r, d);
    __nv_bfloat162 h2 = *(const __nv_bfloat162*)(in + eh);
    __nv_bfloat162 l2 = *(const __nv_bfloat162*)(in + el);
    float vx = __bfloat162float(h2.x) + __bfloat162float(l2.x);
    float vy = __bfloat162float(h2.y) + __bfloat162float(l2.y);
    float s  = vx + vy, sq = vx*vx + vy*vy;
    #pragma unroll
    for (int o = 16; o; o >>= 1){
        s  += __shfl_xor_sync(0xffffffffu, s,  o);
        sq += __shfl_xor_sync(0xffffffffu, sq, o);
    }
    __shared__ float sh[8], shq[8];
    int w = t >> 5, lane = t & 31;
    if (!lane){ sh[w] = s; shq[w] = sq; }
    __syncthreads();
    float ts = 0.f, tq = 0.f;
    #pragma unroll
    for (int i = 0; i < 8; i++){ ts += sh[i]; tq += shq[i]; }
    float mu = ts*(1.f/Dd);
    float rv = rsqrtf(tq*(1.f/Dd) - mu*mu + 1e-5f);
    float ox = (vx-mu)*rv*g[d]   + bta[d];
    float oy = (vy-mu)*rv*g[d+1] + bta[d+1];
    __nv_bfloat16 hx = __float2bfloat16(ox), hy = __float2bfloat16(oy);
    __nv_bfloat162 oh; oh.x = hx; oh.y = hy;
    __nv_bfloat162 ol;
    ol.x = __float2bfloat16(ox - __bfloat162float(hx));
    ol.y = __float2bfloat16(oy - __bfloat162float(hy));
    *(__nv_bfloat162*)(out + eh) = oh;
    *(__nv_bfloat162*)(out + el) = ol;
}

__global__ void embed_kernel(const int* __restrict__ x, const float* __restrict__ emb,
                             const float* __restrict__ pos, __nv_bfloat16* __restrict__ h)
{
    const int token = blockIdx.x, t = threadIdx.x;
    const int s = token & (Ss-1), id = x[token];
    const int blk = token >> 7, r = token & 127, d = 2*t;
    float2 e = *(const float2*)(emb + (long)id*Dd + d);
    float2 p = *(const float2*)(pos + (long)s*Dd + d);
    float vx = e.x + p.x, vy = e.y + p.y;
    __nv_bfloat16 hx = __float2bfloat16(vx), hy = __float2bfloat16(vy);
    __nv_bfloat162 oh; oh.x = hx; oh.y = hy;
    __nv_bfloat162 ol;
    ol.x = __float2bfloat16(vx - __bfloat162float(hx));
    ol.y = __float2bfloat16(vy - __bfloat162float(hy));
    *(__nv_bfloat162*)(h + cidx(16, 0, blk, r, d)) = oh;
    *(__nv_bfloat162*)(h + cidx(16, 1, blk, r, d)) = ol;
}

// partial col sums of hS (chunked) for mean pool
__global__ void colsum_part(const __nv_bfloat16* __restrict__ in, float* __restrict__ part)
{
    const int b = blockIdx.y, ch = blockIdx.x, c = threadIdx.x;
    const int blkg = b*32 + ch;
    float s = 0.f;
    #pragma unroll
    for (int pl = 0; pl < 2; ++pl){
        long base = (((long)(blkg*2+pl)*16 + (c>>5)) << 12) + (((c>>3)&3)*128 << 3) + (c&7);
        #pragma unroll 4
        for (int i = 0; i < 128; ++i)
            s += __bfloat162float(in[base + i*8]);
    }
    part[((long)b*32 + ch)*Dd + c] = s;
}
__global__ void colsum_fin(const float* __restrict__ part, float* __restrict__ out,
                           int cols, int chunks, float scale)
{
    int b = blockIdx.x, c = threadIdx.x;
    float s = 0.f;
    for (int ch = 0; ch < chunks; ch++) s += part[((long)b*chunks+ch)*cols + c];
    out[(long)b*cols + c] = s*scale;
}

__global__ void head1_kernel(const float* __restrict__ pool, const float* __restrict__ Wh1,
                             const float* __restrict__ bh1, float* __restrict__ h1)
{
    int b = blockIdx.x;
    __shared__ float xr[Dd];
    for (int i = threadIdx.x; i < Dd; i += blockDim.x) xr[i] = pool[(long)b*Dd + i];
    __syncthreads();
    int t = threadIdx.x;
    float s = bh1[t];
    #pragma unroll 4
    for (int k = 0; k < Dd; k++) s = fmaf(xr[k], Wh1[(long)k*DHh + t], s);
    h1[(long)b*DHh + t] = fmaxf(s, 0.f);
}
__global__ void head2_kernel(const float* __restrict__ h1, const float* __restrict__ Wh2,
                             const float* __restrict__ bh2, float* __restrict__ out)
{
    int t = threadIdx.x;
    if (t < Bb*CC){
        int b = t / CC, c = t % CC;
        float s = bh2[c];
        #pragma unroll 4
        for (int k = 0; k < DHh; k++) s = fmaf(h1[(long)b*DHh + k], Wh2[(long)k*CC + c], s);
        out[t] = s;
    }
}

// ===================== launch =====================
extern "C" void kernel_launch(void* const* d_in, const int* in_sizes, int n_in,
                              void* d_out, int out_size)
{
    const int*   x   = (const int*)  d_in[0];
    const float* emb = (const float*)d_in[1];
    const float* pos = (const float*)d_in[2];
    const float* Wq  = (const float*)d_in[3];   const float* bq = (const float*)d_in[4];
    const float* Wk  = (const float*)d_in[5];   const float* bk = (const float*)d_in[6];
    const float* Wv  = (const float*)d_in[7];   const float* bv = (const float*)d_in[8];
    const float* Wf  = (const float*)d_in[9];   const float* bf = (const float*)d_in[10];
    const float* Wo  = (const float*)d_in[11];  const float* bo = (const float*)d_in[12];
    const float* lng = (const float*)d_in[13];  const float* lnb= (const float*)d_in[14];
    const float* W1  = (const float*)d_in[15];  const float* b1 = (const float*)d_in[16];
    const float* W2  = (const float*)d_in[17];  const float* b2 = (const float*)d_in[18];
    const float* Wh1 = (const float*)d_in[19];  const float* bh1= (const float*)d_in[20];
    const float* Wh2 = (const float*)d_in[21];  const float* bh2= (const float*)d_in[22];

    __nv_bfloat16 *hS,*qS,*vT,*tS,*pqS,*pkT,*mS,*kvtS,*wv,*wo,*w1,*w2,*wqf,*wkf;
    float *bqf,*bkf,*kvp,*ks,*z,*pp,*pool,*h1;
    cudaGetSymbolAddress((void**)&hS,  g_hS);   cudaGetSymbolAddress((void**)&qS,  g_qS);
    cudaGetSymbolAddress((void**)&vT,  g_vT);   cudaGetSymbolAddress((void**)&tS,  g_tS);
    cudaGetSymbolAddress((void**)&pqS, g_pqS);  cudaGetSymbolAddress((void**)&pkT, g_pkT);
    cudaGetSymbolAddress((void**)&mS,  g_mS);   cudaGetSymbolAddress((void**)&kvtS,g_kvtS);
    cudaGetSymbolAddress((void**)&wv, g_wv); cudaGetSymbolAddress((void**)&wo, g_wo);
    cudaGetSymbolAddress((void**)&w1, g_w1); cudaGetSymbolAddress((void**)&w2, g_w2);
    cudaGetSymbolAddress((void**)&wqf, g_wqf); cudaGetSymbolAddress((void**)&wkf, g_wkf);
    cudaGetSymbolAddress((void**)&bqf, g_bqf); cudaGetSymbolAddress((void**)&bkf, g_bkf);
    cudaGetSymbolAddress((void**)&kvp, g_kvp);
    cudaGetSymbolAddress((void**)&ks,  g_ks);  cudaGetSymbolAddress((void**)&z,   g_z);
    cudaGetSymbolAddress((void**)&pp,  g_pp);  cudaGetSymbolAddress((void**)&pool,g_pool);
    cudaGetSymbolAddress((void**)&h1,  g_h1);

    cudaFuncSetAttribute(gemm_mma<0,0>, cudaFuncAttributeMaxDynamicSharedMemorySize, SMEMG);
    cudaFuncSetAttribute(gemm_mma<0,1>, cudaFuncAttributeMaxDynamicSharedMemorySize, SMEMG);
    cudaFuncSetAttribute(gemm_mma<1,0>, cudaFuncAttributeMaxDynamicSharedMemorySize, SMEMG);
    cudaFuncSetAttribute(gemm_mma<1,1>, cudaFuncAttributeMaxDynamicSharedMemorySize, SMEMG);
    cudaFuncSetAttribute(gemm_mma<3,0>, cudaFuncAttributeMaxDynamicSharedMemorySize, SMEMG);
    cudaFuncSetAttribute(gemm_mma<2,0>, cudaFuncAttributeMaxDynamicSharedMemorySize, SMEMG);
    cudaFuncSetAttribute(gemm_kv,       cudaFuncAttributeMaxDynamicSharedMemorySize, SMEMG);

    dim3 wt(32, 8);
    const dim3 gDD(Dd/128, BS/128, 1);
    const dim3 gDP(1,      BS/128, 1);
    const dim3 gDF(DFf/128,BS/128, 1);
    const dim3 gAT(Dd/128, Ss/128, Bb);
    const dim3 gKV(1, Dd/128, Bb*KVS);
    const long wDD = (long)2*Dd*Dd, wPD = (long)2*Pp*Dd, wDF = (long)2*DFf*Dd;

    // launch order: gemm_mma V (l=0) at launch index 3 so ncu captures a GEMM
    embed_kernel<<<BS,256>>>(x, emb, pos, hS);                          // 0
    wconv<<<dim3(Dd/32, Dd/32, Ll), wt>>>(Wv, wv, Dd, Dd);              // 1
    wfold<<<dim3(Pp/32, Dd/32, 2*Ll), wt>>>(Wq, Wk, Wf, wqf, wkf);      // 2
    gemm_mma<0,1><<<gDD,256,SMEMG>>>(hS, 16, wv, 16, 0, bv, nullptr, vT, Dd, Dd);  // 3 (l=0 V)
    bfold<<<2*Ll, dim3(128,8)>>>(bq, bk, bf, Wf, bqf, bkf);             // 4
    wconv<<<dim3(Dd/32, Dd/32, Ll), wt>>>(Wo, wo, Dd, Dd);              // 5
    wconv<<<dim3(DFf/32, Dd/32,  Ll), wt>>>(W1, w1, Dd, DFf);           // 6
    wconv<<<dim3(Dd/32,  DFf/32, Ll), wt>>>(W2, w2, DFf, Dd);           // 7

    for (int l = 0; l < Ll; l++){
        if (l > 0)
            gemm_mma<0,1><<<gDD,256,SMEMG>>>(hS, 16, wv + l*wDD, 16, 0, bv + l*Dd, nullptr, vT, Dd, Dd);
        gemm_mma<1,0><<<gDP,256,SMEMG>>>(hS, 16, wqf + l*wPD, 16, 0, bqf + l*Pp, nullptr, pqS, Pp, Dd);
        gemm_mma<1,1><<<gDP,256,SMEMG>>>(hS, 16, wkf + l*wPD, 16, 0, bkf + l*Pp, nullptr, pkT, Pp, Dd);
        ksum_kernel<<<dim3(Pp,Bb),256>>>(pkT, ks);
        gemm_kv<<<gKV,256,SMEMG>>>(vT, pkT, kvp);
        reduce_kvt<<<(Bb*Dd*Pp)/256,256>>>(kvp, kvtS);
        z_kernel<<<BS/8,256>>>(pqS, ks, z);
        gemm_mma<3,0><<<gAT,256,SMEMG>>>(pqS, 4, kvtS, 4, (long)2*Dd*Pp, nullptr, z, tS, Dd, Pp);
        gemm_mma<0,0><<<gDD,256,SMEMG>>>(tS, 16, wo + l*wDD, 16, 0, bo + l*Dd, nullptr, qS, Dd, Dd);
        ln_kernel<<<BS,256>>>(qS, lng + l*Dd, lnb + l*Dd, tS);
        gemm_mma<2,0><<<gDF,256,SMEMG>>>(tS, 16, w1 + l*wDF, 16, 0, b1 + l*DFf, nullptr, mS, DFf, Dd);
        gemm_mma<0,0><<<gDD,256,SMEMG>>>(mS, 64, w2 + l*wDF, 64, 0, b2 + l*Dd, nullptr, hS, Dd, DFf);
    }

    colsum_part<<<dim3(32,Bb),Dd>>>(hS, pp);
    colsum_fin <<<Bb,Dd>>>(pp, pool, Dd, 32, 1.0f/Ss);
    head1_kernel<<<Bb,DHh>>>(pool, Wh1, bh1, h1);
    head2_kernel<<<1,32>>>(h1, Wh2, bh2, (float*)d_out);
}

// round 16
// speedup vs baseline: 1.4031x; 1.2525x over previous
#include <cuda_runtime.h>
#include <cuda_bf16.h>
#include <cuda_fp16.h>
#include <math.h>
#include <stdint.h>

#define Bb  8
#define Ss  4096
#define Dd  512
#define Pp  128
#define Ll  4
#define DFf 2048
#define DHh 256
#define CC  2
#define BS  (Bb*Ss)
#define KVS 8

// ===================== PTX helpers (sm_90 core features only) =====================
__device__ __forceinline__ uint32_t smem_to_u32(const void* p) {
    uint32_t a;
    asm("{ .reg .u64 t; cvta.to.shared.u64 t, %1; cvt.u32.u64 %0, t; }" : "=r"(a) : "l"(p));
    return a;
}
#define MBARRIER_INIT(m, c) \
    asm volatile("mbarrier.init.shared.b64 [%0], %1;" :: "r"((uint32_t)(m)), "r"((uint32_t)(c)) : "memory")
#define MBARRIER_EXPECT_TX(m, b) \
    asm volatile("mbarrier.arrive.expect_tx.shared.b64 _, [%0], %1;" :: "r"((uint32_t)(m)), "r"((uint32_t)(b)) : "memory")
#define MBARRIER_ARRIVE(m) \
    asm volatile("mbarrier.arrive.shared.b64 _, [%0];" :: "r"((uint32_t)(m)) : "memory")
#define MBARRIER_WAIT_PARITY(m, par) do { \
    uint32_t _m=(uint32_t)(m), _p=(uint32_t)(par), _d; \
    asm volatile("{\n\t.reg .pred p;\n\tmbarrier.try_wait.parity.acquire.cta.shared::cta.b64 p, [%1], %2;\n\tselp.b32 %0,1,0,p;\n\t}" \
        : "=r"(_d) : "r"(_m), "r"(_p) : "memory"); \
    if (!_d) { \
        asm volatile("{\n\t.reg .pred P1;\n\tWL_%=:\n\tmbarrier.try_wait.parity.acquire.cta.shared::cta.b64 P1, [%0], %1, 0x989680;\n\t@P1 bra.uni WD_%=;\n\tbra.uni WL_%=;\n\tWD_%=:\n\t}" \
            :: "r"(_m), "r"(_p) : "memory"); \
    } \
} while(0)
__device__ __forceinline__ void bulk_g2s(uint32_t dst, const void* src, uint32_t bytes, uint32_t mbar){
    asm volatile("cp.async.bulk.shared::cluster.global.mbarrier::complete_tx::bytes [%0], [%1], %2, [%3];"
        :: "r"(dst), "l"(src), "r"(bytes), "r"(mbar) : "memory");
}
__device__ __forceinline__ void ldsm4(uint32_t* r, uint32_t addr){
    asm volatile("ldmatrix.sync.aligned.m8n8.x4.shared.b16 {%0,%1,%2,%3}, [%4];"
        : "=r"(r[0]),"=r"(r[1]),"=r"(r[2]),"=r"(r[3]) : "r"(addr));
}
template<int FP16>
__device__ __forceinline__ void mma_any(float* d, const uint32_t* a, const uint32_t* b){
    if (FP16)
        asm volatile("mma.sync.aligned.m16n8k16.row.col.f32.f16.f16.f32 "
            "{%0,%1,%2,%3}, {%4,%5,%6,%7}, {%8,%9}, {%0,%1,%2,%3};"
            : "+f"(d[0]),"+f"(d[1]),"+f"(d[2]),"+f"(d[3])
            : "r"(a[0]),"r"(a[1]),"r"(a[2]),"r"(a[3]), "r"(b[0]),"r"(b[1]));
    else
        asm volatile("mma.sync.aligned.m16n8k16.row.col.f32.bf16.bf16.f32 "
            "{%0,%1,%2,%3}, {%4,%5,%6,%7}, {%8,%9}, {%0,%1,%2,%3};"
            : "+f"(d[0]),"+f"(d[1]),"+f"(d[2]),"+f"(d[3])
            : "r"(a[0]),"r"(a[1]),"r"(a[2]),"r"(a[3]), "r"(b[0]),"r"(b[1]));
}

// ===================== chunk-packed layout =====================
__device__ __forceinline__ long cidx(int KC, int pl, int blk, int r, int k){
    return (((long)(blk*2 + pl)*KC + (k>>5)) << 12) + ((((k>>3)&3)*128 + r) << 3) + (k&7);
}

// ===================== device globals =====================
__device__ __align__(256) __nv_bfloat16 g_hS [2*(size_t)BS*Dd];
__device__ __align__(256) __nv_bfloat16 g_qS [2*(size_t)BS*Dd];
__device__ __align__(256) __nv_bfloat16 g_vT [2*(size_t)BS*Dd];
__device__ __align__(256) __nv_bfloat16 g_tS [2*(size_t)BS*Dd];   // attn-out bf16, then ln-out fp16(hi)
__device__ __align__(256) __nv_bfloat16 g_pqS[2*(size_t)BS*Pp];
__device__ __align__(256) __nv_bfloat16 g_pkT[2*(size_t)BS*Pp];
__device__ __align__(256) __nv_bfloat16 g_mS [2*(size_t)BS*DFf];  // fp16(hi) bits
__device__ __align__(256) __nv_bfloat16 g_kvtS[(size_t)Bb*2*Dd*Pp];
__device__ __align__(256) __nv_bfloat16 g_wv[(size_t)Ll*2*Dd*Dd];
__device__ __align__(256) __nv_bfloat16 g_wo[(size_t)Ll*2*Dd*Dd];
__device__ __align__(256) __nv_bfloat16 g_w1[(size_t)Ll*2*DFf*Dd];  // fp16 bits
__device__ __align__(256) __nv_bfloat16 g_w2[(size_t)Ll*2*Dd*DFf];  // fp16 bits
__device__ __align__(256) __nv_bfloat16 g_wqf[(size_t)Ll*2*Pp*Dd];
__device__ __align__(256) __nv_bfloat16 g_wkf[(size_t)Ll*2*Pp*Dd];
__device__ float g_bqf[Ll*Pp];
__device__ float g_bkf[Ll*Pp];
__device__ float g_kvp[(size_t)Bb*KVS*Pp*Dd];
__device__ float g_ks [Bb*Pp];
__device__ float g_z  [BS];
__device__ float g_pp [Bb*32*Dd];
__device__ float g_pool[Bb*Dd];
__device__ float g_h1 [Bb*DHh];

__device__ __forceinline__ float gelu_tanh(float x){
    float u = 0.7978845608028654f*(x + 0.044715f*x*x*x);
    return 0.5f*x*(1.0f + tanhf(u));
}

// ===================== bulk-pipelined split HMMA GEMM =====================
// bf16 3-pass: stage [Ah 8K][Al 8K][Bh 8K][Bl 8K] = 32KB; NSTG=3 -> 97KB -> 2 CTAs/SM.
// fp16 2-pass: stage [Ah 8K][Bh 8K][Bl 8K] = 24KB; NSTG=3 -> 73KB -> 2 CTAs/SM.
#define NSTG 3

// EPI 0:+bias 1:+bias,elu+1 2:+bias,gelu 3:*1/(aux+eps)
// TOUT 0:chunked [M,N], 1:transposed chunked [N rows][Ss]
// FP16 1: fp16 operands, 2-pass (ah*bh + ah*bl); 0: bf16, 3-pass
// OUTH 1: TOUT0 epilogue writes fp16 hi-plane only
template<int EPI, int TOUT, int FP16, int OUTH>
__global__ void __launch_bounds__(256, 2)
gemm_mma(const __nv_bfloat16* __restrict__ A, int KCa,
         const __nv_bfloat16* __restrict__ Bw, int KCb, long b_batch,
         const float* __restrict__ bias, const float* __restrict__ aux,
         __nv_bfloat16* __restrict__ C, int N, int K)
{
    constexpr uint32_t STGB = FP16 ? 24576u : 32768u;
    constexpr uint32_t BOFF = FP16 ? 8192u  : 16384u;
    extern __shared__ __align__(1024) char smem[];
    const uint32_t sb = smem_to_u32(smem);
    const int tid = threadIdx.x, wid = tid >> 5, lane = tid & 31;
    const int rowblk = blockIdx.z*gridDim.y + blockIdx.y;
    const int nblk = blockIdx.x;
    const int row0 = rowblk*128, col0 = nblk*128;
    const int niter = K >> 5;
    const uint32_t FULL0 = sb, EMPTY0 = sb + 32;
    const uint32_t STG0 = sb + 1024;
    const __nv_bfloat16* Bt = Bw + (long)blockIdx.z*b_batch;

    if (tid == 0){
        #pragma unroll
        for (int s = 0; s < NSTG; ++s){ MBARRIER_INIT(FULL0+8*s, 1); MBARRIER_INIT(EMPTY0+8*s, 256); }
    }
    __syncthreads();

    auto issue = [&](int j){
        const int s = j % NSTG;
        if (j >= NSTG) MBARRIER_WAIT_PARITY(EMPTY0+8*s, ((j/NSTG)-1)&1);
        MBARRIER_EXPECT_TX(FULL0+8*s, STGB);
        const uint32_t dst = STG0 + s*STGB;
        bulk_g2s(dst, A + (((long)(rowblk*2)*KCa + j) << 12), 8192u, FULL0+8*s);
        if (!FP16)
            bulk_g2s(dst + 8192, A + (((long)(rowblk*2+1)*KCa + j) << 12), 8192u, FULL0+8*s);
        bulk_g2s(dst + BOFF,        Bt + (((long)(nblk*2  )*KCb + j) << 12), 8192u, FULL0+8*s);
        bulk_g2s(dst + BOFF + 8192, Bt + (((long)(nblk*2+1)*KCb + j) << 12), 8192u, FULL0+8*s);
    };
    if (tid == 0){
        const int pro = (niter < NSTG-1) ? niter : NSTG-1;
        for (int j = 0; j < pro; ++j) issue(j);
    }

    float acc[2][8][4];
    #pragma unroll
    for (int mt=0;mt<2;mt++)
        #pragma unroll
        for (int ni=0;ni<8;ni++)
            #pragma unroll
            for (int r=0;r<4;r++) acc[mt][ni][r]=0.f;

    const int wm = (wid >> 1)*32, wn = (wid & 1)*64;
    const int a_mrow = wm + ((lane>>3)&1)*8 + (lane&7);
    const int a_kc   = (lane>>4);
    const int b_nrow = wn + ((lane>>4)&1)*8 + (lane&7);
    const int b_kc   = ((lane>>3)&1);

    for (int it = 0; it < niter; ++it){
        const int s = it % NSTG;
        if (tid == 0 && it + NSTG-1 < niter) issue(it + NSTG-1);
        MBARRIER_WAIT_PARITY(FULL0+8*s, (it/NSTG)&1);
        const uint32_t stg = STG0 + s*STGB;
        #pragma unroll
        for (int step = 0; step < 2; ++step){
            const int ga = a_kc + 2*step, gb = b_kc + 2*step;
            uint32_t ah[2][4], al[2][4];
            #pragma unroll
            for (int mt = 0; mt < 2; ++mt){
                const uint32_t aoff = stg + (uint32_t)(((ga*128) + a_mrow + mt*16)*16);
                ldsm4(ah[mt], aoff);
                if (!FP16) ldsm4(al[mt], aoff + 8192);
            }
            #pragma unroll
            for (int nt4 = 0; nt4 < 4; ++nt4){
                const uint32_t boff = stg + BOFF + (uint32_t)(((gb*128) + b_nrow + nt4*16)*16);
                uint32_t bh[4], bl[4];
                ldsm4(bh, boff);
                ldsm4(bl, boff + 8192);
                #pragma unroll
                for (int mt = 0; mt < 2; ++mt){
                    mma_any<FP16>(acc[mt][2*nt4  ], ah[mt], bh);
                    mma_any<FP16>(acc[mt][2*nt4+1], ah[mt], bh+2);
                    if (!FP16){
                        mma_any<FP16>(acc[mt][2*nt4  ], al[mt], bh);
                        mma_any<FP16>(acc[mt][2*nt4+1], al[mt], bh+2);
                    }
                    mma_any<FP16>(acc[mt][2*nt4  ], ah[mt], bl);
                    mma_any<FP16>(acc[mt][2*nt4+1], ah[mt], bl+2);
                }
            }
        }
        MBARRIER_ARRIVE(EMPTY0+8*s);
    }

    // ---- epilogue ----
    float bv0[8], bv1[8];
    if (EPI != 3){
        #pragma unroll
        for (int ni = 0; ni < 8; ++ni){
            const int col = col0 + wn + ni*8 + (lane&3)*2;
            bv0[ni] = bias[col]; bv1[ni] = bias[col+1];
        }
    }

    if (TOUT == 0){
        const int KCo = N >> 5;
        #pragma unroll
        for (int mt = 0; mt < 2; ++mt){
            #pragma unroll
            for (int h = 0; h < 2; ++h){
                const long row = row0 + wm + mt*16 + h*8 + (lane>>2);
                float sc = 1.f;
                if (EPI == 3) sc = 1.f/(aux[row] + 1e-6f);
                const int r = (int)(row & 127);
                #pragma unroll
                for (int ni = 0; ni < 8; ++ni){
                    const int col = col0 + wn + ni*8 + (lane&3)*2;
                    float c0 = acc[mt][ni][2*h], c1 = acc[mt][ni][2*h+1];
                    if (EPI != 3){ c0 += bv0[ni]; c1 += bv1[ni]; }
                    if (EPI == 1){ c0 = (c0>0.f)?(c0+1.f):expf(c0); c1 = (c1>0.f)?(c1+1.f):expf(c1); }
                    if (EPI == 2){ c0 = gelu_tanh(c0); c1 = gelu_tanh(c1); }
                    if (EPI == 3){ c0 *= sc; c1 *= sc; }
                    if (OUTH){
                        __half2 vh = __floats2half2_rn(c0, c1);
                        *(__half2*)((__half*)C + cidx(KCo, 0, rowblk, r, col)) = vh;
                    } else {
                        __nv_bfloat16 h0 = __float2bfloat16(c0), h1 = __float2bfloat16(c1);
                        __nv_bfloat162 vh; vh.x = h0; vh.y = h1;
                        __nv_bfloat162 vl;
                        vl.x = __float2bfloat16(c0 - __bfloat162float(h0));
                        vl.y = __float2bfloat16(c1 - __bfloat162float(h1));
                        *(__nv_bfloat162*)(C + cidx(KCo, 0, rowblk, r, col)) = vh;
                        *(__nv_bfloat162*)(C + cidx(KCo, 1, rowblk, r, col)) = vl;
                    }
                }
            }
        }
    } else {
        #pragma unroll
        for (int mt = 0; mt < 2; ++mt)
            #pragma unroll
            for (int ni = 0; ni < 8; ++ni){
                #pragma unroll
                for (int h = 0; h < 2; ++h){
                    float c0 = acc[mt][ni][2*h] + bv0[ni];
                    float c1 = acc[mt][ni][2*h+1] + bv1[ni];
                    if (EPI == 1){ c0 = (c0>0.f)?(c0+1.f):expf(c0); c1 = (c1>0.f)?(c1+1.f):expf(c1); }
                    acc[mt][ni][2*h] = c0; acc[mt][ni][2*h+1] = c1;
                }
            }
        __syncthreads();
        __nv_bfloat16* sT = (__nv_bfloat16*)(smem + 1024);   // [128 col][136 tok]
        const int st0 = (int)(row0 & (Ss-1));
        const int cb = col0 >> 7;
        const int KCss = Ss >> 5;
        __nv_bfloat16* tB = C + (long)(row0 >> 12)*2*(long)N*Ss;
        #pragma unroll
        for (int pl = 0; pl < 2; ++pl){
            #pragma unroll
            for (int mt = 0; mt < 2; ++mt){
                #pragma unroll
                for (int h = 0; h < 2; ++h){
                    const int tok = wm + mt*16 + h*8 + (lane>>2);
                    #pragma unroll
                    for (int ni = 0; ni < 8; ++ni){
                        const int col = wn + ni*8 + (lane&3)*2;
                        float c0 = acc[mt][ni][2*h], c1 = acc[mt][ni][2*h+1];
                        __nv_bfloat16 h0 = __float2bfloat16(c0), h1 = __float2bfloat16(c1);
                        if (pl){
                            h0 = __float2bfloat16(c0 - __bfloat162float(h0));
                            h1 = __float2bfloat16(c1 - __bfloat162float(h1));
                        }
                        sT[col*136 + tok]     = h0;
                        sT[(col+1)*136 + tok] = h1;
                    }
                }
            }
            __syncthreads();
            #pragma unroll
            for (int j = 0; j < 8; ++j){
                const int idx = j*256 + tid;
                const int oct = idx >> 7, n = idx & 127;
                uint4 v = *(const uint4*)(sT + n*136 + oct*8);
                const int st = st0 + oct*8;
                long e = (((long)(cb*2+pl)*KCss + (st>>5)) << 12) + ((((st>>3)&3)*128 + n) << 3);
                *(uint4*)(tB + e) = v;
            }
            __syncthreads();
        }
    }
}

// ===================== kv gemm: kv^T[b] = vT[b] @ pkT[b]^T, split-K fp32 partials =====================
#define STGKV 32768
__global__ void __launch_bounds__(256, 2)
gemm_kv(const __nv_bfloat16* __restrict__ vT, const __nv_bfloat16* __restrict__ pkT,
        float* __restrict__ part)
{
    extern __shared__ __align__(1024) char smem[];
    const uint32_t sb = smem_to_u32(smem);
    const int tid = threadIdx.x, wid = tid >> 5, lane = tid & 31;
    const int bz = blockIdx.z, b = bz >> 3, sp = bz & (KVS-1);
    const int ablk = blockIdx.y, row0 = ablk*128;
    const int niter = (Ss/KVS) >> 5;      // 16
    const int kchunk0 = sp*((Ss/KVS) >> 5);
    const uint32_t FULL0 = sb, EMPTY0 = sb + 32;
    const uint32_t STG0 = sb + 1024;
    const __nv_bfloat16* A  = vT  + (long)b*2*Dd*Ss;
    const __nv_bfloat16* Bp = pkT + (long)b*2*Pp*Ss;

    if (tid == 0){
        #pragma unroll
        for (int s = 0; s < NSTG; ++s){ MBARRIER_INIT(FULL0+8*s, 1); MBARRIER_INIT(EMPTY0+8*s, 256); }
    }
    __syncthreads();

    auto issue = [&](int j){
        const int s = j % NSTG;
        if (j >= NSTG) MBARRIER_WAIT_PARITY(EMPTY0+8*s, ((j/NSTG)-1)&1);
        MBARRIER_EXPECT_TX(FULL0+8*s, 32768u);
        const uint32_t dst = STG0 + s*STGKV;
        bulk_g2s(dst,         A  + (((long)(ablk*2  )*(Ss>>5) + kchunk0 + j) << 12), 8192u, FULL0+8*s);
        bulk_g2s(dst + 8192,  A  + (((long)(ablk*2+1)*(Ss>>5) + kchunk0 + j) << 12), 8192u, FULL0+8*s);
        bulk_g2s(dst + 16384, Bp + (((long)(0      )*(Ss>>5) + kchunk0 + j) << 12), 8192u, FULL0+8*s);
        bulk_g2s(dst + 24576, Bp + (((long)(1      )*(Ss>>5) + kchunk0 + j) << 12), 8192u, FULL0+8*s);
    };
    if (tid == 0){ for (int j = 0; j < NSTG-1; ++j) issue(j); }

    float acc[2][8][4];
    #pragma unroll
    for (int mt=0;mt<2;mt++)
        #pragma unroll
        for (int ni=0;ni<8;ni++)
            #pragma unroll
            for (int r=0;r<4;r++) acc[mt][ni][r]=0.f;

    const int wm = (wid >> 1)*32, wn = (wid & 1)*64;
    const int a_mrow = wm + ((lane>>3)&1)*8 + (lane&7);
    const int a_kc   = (lane>>4);
    const int b_nrow = wn + ((lane>>4)&1)*8 + (lane&7);
    const int b_kc   = ((lane>>3)&1);

    for (int it = 0; it < niter; ++it){
        const int s = it % NSTG;
        if (tid == 0 && it + NSTG-1 < niter) issue(it + NSTG-1);
        MBARRIER_WAIT_PARITY(FULL0+8*s, (it/NSTG)&1);
        const uint32_t stg = STG0 + s*STGKV;
        #pragma unroll
        for (int step = 0; step < 2; ++step){
            const int ga = a_kc + 2*step, gb = b_kc + 2*step;
            uint32_t ah[2][4], al[2][4];
            #pragma unroll
            for (int mt = 0; mt < 2; ++mt){
                const uint32_t aoff = stg + (uint32_t)(((ga*128) + a_mrow + mt*16)*16);
                ldsm4(ah[mt], aoff);
                ldsm4(al[mt], aoff + 8192);
            }
            #pragma unroll
            for (int nt4 = 0; nt4 < 4; ++nt4){
                const uint32_t boff = stg + 16384 + (uint32_t)(((gb*128) + b_nrow + nt4*16)*16);
                uint32_t bh[4], bl[4];
                ldsm4(bh, boff);
                ldsm4(bl, boff + 8192);
                #pragma unroll
                for (int mt = 0; mt < 2; ++mt){
                    mma_any<0>(acc[mt][2*nt4  ], ah[mt], bh);
                    mma_any<0>(acc[mt][2*nt4+1], ah[mt], bh+2);
                    mma_any<0>(acc[mt][2*nt4  ], al[mt], bh);
                    mma_any<0>(acc[mt][2*nt4+1], al[mt], bh+2);
                    mma_any<0>(acc[mt][2*nt4  ], ah[mt], bl);
                    mma_any<0>(acc[mt][2*nt4+1], ah[mt], bl+2);
                }
            }
        }
        MBARRIER_ARRIVE(EMPTY0+8*s);
    }

    float* Cb = part + (long)bz*Dd*Pp;
    #pragma unroll
    for (int mt = 0; mt < 2; ++mt){
        #pragma unroll
        for (int h = 0; h < 2; ++h){
            const int row = row0 + wm + mt*16 + h*8 + (lane>>2);
            #pragma unroll
            for (int ni = 0; ni < 8; ++ni){
                const int col = wn + ni*8 + (lane&3)*2;
                *(float2*)(Cb + (long)row*Pp + col) =
                    make_float2(acc[mt][ni][2*h], acc[mt][ni][2*h+1]);
            }
        }
    }
}

// reduce partials -> kvtS chunked [D rows][P] per batch
__global__ void reduce_kvt(const float* __restrict__ part, __nv_bfloat16* __restrict__ kvt)
{
    long i = (long)blockIdx.x*256 + threadIdx.x;
    int b = (int)(i / (Dd*Pp)); int r0 = (int)(i % (Dd*Pp));
    int d = r0 >> 7, p = r0 & 127;
    const float* q = part + ((long)b*KVS)*Dd*Pp + r0;
    float s = 0.f;
    #pragma unroll
    for (int j = 0; j < KVS; j++) s += q[(long)j*Dd*Pp];
    __nv_bfloat16 h = __float2bfloat16(s);
    __nv_bfloat16* base = kvt + (long)b*2*Dd*Pp;
    base[cidx(4, 0, d>>7, d&127, p)] = h;
    base[cidx(4, 1, d>>7, d&127, p)] = __float2bfloat16(s - __bfloat162float(h));
}

// ===================== weight conversion (bf16 split) =====================
__global__ void wconv(const float* __restrict__ W, __nv_bfloat16* __restrict__ out, int K, int N)
{
    __shared__ float t[32][33];
    const int n0 = blockIdx.x*32, k0 = blockIdx.y*32, l = blockIdx.z;
    const float* Wl = W + (long)l*K*N;
    __nv_bfloat16* ob = out + (long)l*2*N*K;
    const int KC = K >> 5;
    for (int i = threadIdx.y; i < 32; i += 8)
        t[i][threadIdx.x] = Wl[(long)(k0+i)*N + n0 + threadIdx.x];
    __syncthreads();
    for (int i = threadIdx.y; i < 32; i += 8) {
        float v = t[threadIdx.x][i];
        const int n = n0 + i, k = k0 + threadIdx.x;
        __nv_bfloat16 h = __float2bfloat16(v);
        ob[cidx(KC, 0, n>>7, n&127, k)] = h;
        ob[cidx(KC, 1, n>>7, n&127, k)] = __float2bfloat16(v - __bfloat162float(h));
    }
}

// ===================== weight conversion (fp16 split) =====================
__global__ void wconv_h(const float* __restrict__ W, __nv_bfloat16* __restrict__ out_raw, int K, int N)
{
    __shared__ float t[32][33];
    const int n0 = blockIdx.x*32, k0 = blockIdx.y*32, l = blockIdx.z;
    const float* Wl = W + (long)l*K*N;
    __half* ob = (__half*)(out_raw + (long)l*2*N*K);
    const int KC = K >> 5;
    for (int i = threadIdx.y; i < 32; i += 8)
        t[i][threadIdx.x] = Wl[(long)(k0+i)*N + n0 + threadIdx.x];
    __syncthreads();
    for (int i = threadIdx.y; i < 32; i += 8) {
        float v = t[threadIdx.x][i];
        const int n = n0 + i, k = k0 + threadIdx.x;
        __half h = __float2half_rn(v);
        ob[cidx(KC, 0, n>>7, n&127, k)] = h;
        ob[cidx(KC, 1, n>>7, n&127, k)] = __float2half_rn(v - __half2float(h));
    }
}

// folded feature weights
__global__ void wfold(const float* __restrict__ Wq, const float* __restrict__ Wk,
                      const float* __restrict__ Wf,
                      __nv_bfloat16* __restrict__ oq, __nv_bfloat16* __restrict__ ok)
{
    const int which = blockIdx.z & 1, l = blockIdx.z >> 1;
    const float* Wa  = (which ? Wk : Wq) + (long)l*Dd*Dd;
    const float* Wfl = Wf + (long)l*Dd*Pp;
    __nv_bfloat16* out = (which ? ok : oq) + (long)l*2*Pp*Dd;
    const int p0 = blockIdx.x*32, c0 = blockIdx.y*32;
    __shared__ float a[32][33], bsm[32][33];
    const int tx = threadIdx.x, ty = threadIdx.y;
    float acc[4] = {0.f,0.f,0.f,0.f};
    for (int m0 = 0; m0 < Dd; m0 += 32){
        for (int i = ty; i < 32; i += 8) a[i][tx]   = Wa[(long)(c0+i)*Dd + m0+tx];
        for (int i = ty; i < 32; i += 8) bsm[i][tx] = Wfl[(long)(m0+i)*Pp + p0+tx];
        __syncthreads();
        #pragma unroll
        for (int mm = 0; mm < 32; ++mm){
            float bv = bsm[mm][tx];
            #pragma unroll
            for (int i = 0; i < 4; ++i) acc[i] = fmaf(a[ty+8*i][mm], bv, acc[i]);
        }
        __syncthreads();
    }
    #pragma unroll
    for (int i = 0; i < 4; ++i){
        const int k = c0 + ty + 8*i, n = p0 + tx;
        __nv_bfloat16 h = __float2bfloat16(acc[i]);
        out[cidx(16, 0, 0, n, k)] = h;
        out[cidx(16, 1, 0, n, k)] = __float2bfloat16(acc[i] - __bfloat162float(h));
    }
}

// folded bias
__global__ void bfold(const float* __restrict__ bq, const float* __restrict__ bk,
                      const float* __restrict__ bf, const float* __restrict__ Wf,
                      float* __restrict__ obq, float* __restrict__ obk)
{
    const int which = blockIdx.x & 1, l = blockIdx.x >> 1;
    const float* bb  = (which ? bk : bq) + l*Dd;
    const float* Wfl = Wf + (long)l*Dd*Pp;
    const int p = threadIdx.x, ty = threadIdx.y;   // block (128, 8)
    float s = 0.f;
    #pragma unroll 8
    for (int c = ty; c < Dd; c += 8)
        s = fmaf(bb[c], Wfl[(long)c*Pp + p], s);
    __shared__ float sh[8][128];
    sh[ty][p] = s;
    __syncthreads();
    if (ty == 0){
        float t = bf[l*Pp + p];
        #pragma unroll
        for (int i = 0; i < 8; i++) t += sh[i][p];
        (which ? obk : obq)[l*Pp + p] = t;
    }
}

// ksum[b,p] = sum_s pkT(hi+lo)
__global__ void ksum_kernel(const __nv_bfloat16* __restrict__ pkT, float* __restrict__ ks)
{
    const int p = blockIdx.x, b = blockIdx.y, t = threadIdx.x;
    const __nv_bfloat16* base = pkT + (long)b*2*Pp*Ss;
    float s = 0.f;
    for (int o = t; o < 512; o += 256){
        #pragma unroll
        for (int pl = 0; pl < 2; ++pl){
            long e = (((long)(pl*(Ss>>5)) + (o>>2)) << 12) + (((o&3)*128 + p) << 3);
            uint4 v = *(const uint4*)(base + e);
            const __nv_bfloat162* pv = (const __nv_bfloat162*)&v;
            #pragma unroll
            for (int q = 0; q < 4; ++q)
                s += __bfloat162float(pv[q].x) + __bfloat162float(pv[q].y);
        }
    }
    __shared__ float sh[256];
    sh[t] = s; __syncthreads();
    #pragma unroll
    for (int o = 128; o > 0; o >>= 1){
        if (t < o) sh[t] += sh[t+o];
        __syncthreads();
    }
    if (!t) ks[b*Pp + p] = sh[0];
}

// z[b,s] = dot(pq(hi+lo), ksum)
__global__ void z_kernel(const __nv_bfloat16* __restrict__ pq, const float* __restrict__ ksum,
                         float* __restrict__ z)
{
    int gw = (int)((blockIdx.x*(long)blockDim.x + threadIdx.x) >> 5);
    int lane = threadIdx.x & 31;
    if (gw >= BS) return;
    const int b = gw >> 12, blk = gw >> 7, r = gw & 127;
    const float* kr = ksum + b*Pp;
    const int p0 = lane*4;
    float s = 0.f;
    #pragma unroll
    for (int pl = 0; pl < 2; ++pl){
        long e = (((long)(blk*2+pl)*4 + (p0>>5)) << 12) + ((((p0>>3)&3)*128 + r) << 3) + (p0&7);
        uint2 v = *(const uint2*)(pq + e);
        const __nv_bfloat162* pv = (const __nv_bfloat162*)&v;
        s = fmaf(__bfloat162float(pv[0].x), kr[p0],   s);
        s = fmaf(__bfloat162float(pv[0].y), kr[p0+1], s);
        s = fmaf(__bfloat162float(pv[1].x), kr[p0+2], s);
        s = fmaf(__bfloat162float(pv[1].y), kr[p0+3], s);
    }
    #pragma unroll
    for (int o = 16; o; o >>= 1) s += __shfl_xor_sync(0xffffffffu, s, o);
    if (!lane) z[gw] = s;
}

// layernorm: bf16 split in (qS), fp16 hi-plane out (tS) for the fp16 FFN path
__global__ void ln_kernel(const __nv_bfloat16* __restrict__ in, const float* __restrict__ g,
                          const float* __restrict__ bta, __nv_bfloat16* __restrict__ out_raw)
{
    const int row = blockIdx.x, t = threadIdx.x;
    const int blk = row >> 7, r = row & 127, d = 2*t;
    const long eh = cidx(16, 0, blk, r, d);
    const long el = cidx(16, 1, blk, r, d);
    __nv_bfloat162 h2 = *(const __nv_bfloat162*)(in + eh);
    __nv_bfloat162 l2 = *(const __nv_bfloat162*)(in + el);
    float vx = __bfloat162float(h2.x) + __bfloat162float(l2.x);
    float vy = __bfloat162float(h2.y) + __bfloat162float(l2.y);
    float s  = vx + vy, sq = vx*vx + vy*vy;
    #pragma unroll
    for (int o = 16; o; o >>= 1){
        s  += __shfl_xor_sync(0xffffffffu, s,  o);
        sq += __shfl_xor_sync(0xffffffffu, sq, o);
    }
    __shared__ float sh[8], shq[8];
    int w = t >> 5, lane = t & 31;
    if (!lane){ sh[w] = s; shq[w] = sq; }
    __syncthreads();
    float ts = 0.f, tq = 0.f;
    #pragma unroll
    for (int i = 0; i < 8; i++){ ts += sh[i]; tq += shq[i]; }
    float mu = ts*(1.f/Dd);
    float rv = rsqrtf(tq*(1.f/Dd) - mu*mu + 1e-5f);
    float ox = (vx-mu)*rv*g[d]   + bta[d];
    float oy = (vy-mu)*rv*g[d+1] + bta[d+1];
    *(__half2*)((__half*)out_raw + eh) = __floats2half2_rn(ox, oy);
}

__global__ void embed_kernel(const int* __restrict__ x, const float* __restrict__ emb,
                             const float* __restrict__ pos, __nv_bfloat16* __restrict__ h)
{
    const int token = blockIdx.x, t = threadIdx.x;
    const int s = token & (Ss-1), id = x[token];
    const int blk = token >> 7, r = token & 127, d = 2*t;
    float2 e = *(const float2*)(emb + (long)id*Dd + d);
    float2 p = *(const float2*)(pos + (long)s*Dd + d);
    float vx = e.x + p.x, vy = e.y + p.y;
    __nv_bfloat16 hx = __float2bfloat16(vx), hy = __float2bfloat16(vy);
    __nv_bfloat162 oh; oh.x = hx; oh.y = hy;
    __nv_bfloat162 ol;
    ol.x = __float2bfloat16(vx - __bfloat162float(hx));
    ol.y = __float2bfloat16(vy - __bfloat162float(hy));
    *(__nv_bfloat162*)(h + cidx(16, 0, blk, r, d)) = oh;
    *(__nv_bfloat162*)(h + cidx(16, 1, blk, r, d)) = ol;
}

// partial col sums of hS (chunked) for mean pool
__global__ void colsum_part(const __nv_bfloat16* __restrict__ in, float* __restrict__ part)
{
    const int b = blockIdx.y, ch = blockIdx.x, c = threadIdx.x;
    const int blkg = b*32 + ch;
    float s = 0.f;
    #pragma unroll
    for (int pl = 0; pl < 2; ++pl){
        long base = (((long)(blkg*2+pl)*16 + (c>>5)) << 12) + (((c>>3)&3)*128 << 3) + (c&7);
        #pragma unroll 4
        for (int i = 0; i < 128; ++i)
            s += __bfloat162float(in[base + i*8]);
    }
    part[((long)b*32 + ch)*Dd + c] = s;
}
__global__ void colsum_fin(const float* __restrict__ part, float* __restrict__ out,
                           int cols, int chunks, float scale)
{
    int b = blockIdx.x, c = threadIdx.x;
    float s = 0.f;
    for (int ch = 0; ch < chunks; ch++) s += part[((long)b*chunks+ch)*cols + c];
    out[(long)b*cols + c] = s*scale;
}

__global__ void head1_kernel(const float* __restrict__ pool, const float* __restrict__ Wh1,
                             const float* __restrict__ bh1, float* __restrict__ h1)
{
    int b = blockIdx.x;
    __shared__ float xr[Dd];
    for (int i = threadIdx.x; i < Dd; i += blockDim.x) xr[i] = pool[(long)b*Dd + i];
    __syncthreads();
    int t = threadIdx.x;
    float s = bh1[t];
    #pragma unroll 4
    for (int k = 0; k < Dd; k++) s = fmaf(xr[k], Wh1[(long)k*DHh + t], s);
    h1[(long)b*DHh + t] = fmaxf(s, 0.f);
}
__global__ void head2_kernel(const float* __restrict__ h1, const float* __restrict__ Wh2,
                             const float* __restrict__ bh2, float* __restrict__ out)
{
    int t = threadIdx.x;
    if (t < Bb*CC){
        int b = t / CC, c = t % CC;
        float s = bh2[c];
        #pragma unroll 4
        for (int k = 0; k < DHh; k++) s = fmaf(h1[(long)b*DHh + k], Wh2[(long)k*CC + c], s);
        out[t] = s;
    }
}

// ===================== launch =====================
extern "C" void kernel_launch(void* const* d_in, const int* in_sizes, int n_in,
                              void* d_out, int out_size)
{
    const int*   x   = (const int*)  d_in[0];
    const float* emb = (const float*)d_in[1];
    const float* pos = (const float*)d_in[2];
    const float* Wq  = (const float*)d_in[3];   const float* bq = (const float*)d_in[4];
    const float* Wk  = (const float*)d_in[5];   const float* bk = (const float*)d_in[6];
    const float* Wv  = (const float*)d_in[7];   const float* bv = (const float*)d_in[8];
    const float* Wf  = (const float*)d_in[9];   const float* bf = (const float*)d_in[10];
    const float* Wo  = (const float*)d_in[11];  const float* bo = (const float*)d_in[12];
    const float* lng = (const float*)d_in[13];  const float* lnb= (const float*)d_in[14];
    const float* W1  = (const float*)d_in[15];  const float* b1 = (const float*)d_in[16];
    const float* W2  = (const float*)d_in[17];  const float* b2 = (const float*)d_in[18];
    const float* Wh1 = (const float*)d_in[19];  const float* bh1= (const float*)d_in[20];
    const float* Wh2 = (const float*)d_in[21];  const float* bh2= (const float*)d_in[22];

    __nv_bfloat16 *hS,*qS,*vT,*tS,*pqS,*pkT,*mS,*kvtS,*wv,*wo,*w1,*w2,*wqf,*wkf;
    float *bqf,*bkf,*kvp,*ks,*z,*pp,*pool,*h1;
    cudaGetSymbolAddress((void**)&hS,  g_hS);   cudaGetSymbolAddress((void**)&qS,  g_qS);
    cudaGetSymbolAddress((void**)&vT,  g_vT);   cudaGetSymbolAddress((void**)&tS,  g_tS);
    cudaGetSymbolAddress((void**)&pqS, g_pqS);  cudaGetSymbolAddress((void**)&pkT, g_pkT);
    cudaGetSymbolAddress((void**)&mS,  g_mS);   cudaGetSymbolAddress((void**)&kvtS,g_kvtS);
    cudaGetSymbolAddress((void**)&wv, g_wv); cudaGetSymbolAddress((void**)&wo, g_wo);
    cudaGetSymbolAddress((void**)&w1, g_w1); cudaGetSymbolAddress((void**)&w2, g_w2);
    cudaGetSymbolAddress((void**)&wqf, g_wqf); cudaGetSymbolAddress((void**)&wkf, g_wkf);
    cudaGetSymbolAddress((void**)&bqf, g_bqf); cudaGetSymbolAddress((void**)&bkf, g_bkf);
    cudaGetSymbolAddress((void**)&kvp, g_kvp);
    cudaGetSymbolAddress((void**)&ks,  g_ks);  cudaGetSymbolAddress((void**)&z,   g_z);
    cudaGetSymbolAddress((void**)&pp,  g_pp);  cudaGetSymbolAddress((void**)&pool,g_pool);
    cudaGetSymbolAddress((void**)&h1,  g_h1);

    const int SMEM3 = 1024 + NSTG*32768;   // bf16 3-pass
    const int SMEM2 = 1024 + NSTG*24576;   // fp16 2-pass
    cudaFuncSetAttribute(gemm_mma<0,0,0,0>, cudaFuncAttributeMaxDynamicSharedMemorySize, SMEM3);
    cudaFuncSetAttribute(gemm_mma<0,1,0,0>, cudaFuncAttributeMaxDynamicSharedMemorySize, SMEM3);
    cudaFuncSetAttribute(gemm_mma<1,0,0,0>, cudaFuncAttributeMaxDynamicSharedMemorySize, SMEM3);
    cudaFuncSetAttribute(gemm_mma<1,1,0,0>, cudaFuncAttributeMaxDynamicSharedMemorySize, SMEM3);
    cudaFuncSetAttribute(gemm_mma<3,0,0,0>, cudaFuncAttributeMaxDynamicSharedMemorySize, SMEM3);
    cudaFuncSetAttribute(gemm_mma<2,0,1,1>, cudaFuncAttributeMaxDynamicSharedMemorySize, SMEM2);
    cudaFuncSetAttribute(gemm_mma<0,0,1,0>, cudaFuncAttributeMaxDynamicSharedMemorySize, SMEM2);
    cudaFuncSetAttribute(gemm_kv,           cudaFuncAttributeMaxDynamicSharedMemorySize, SMEM3);

    dim3 wt(32, 8);
    const dim3 gDD(Dd/128, BS/128, 1);
    const dim3 gDP(1,      BS/128, 1);
    const dim3 gDF(DFf/128,BS/128, 1);
    const dim3 gAT(Dd/128, Ss/128, Bb);
    const dim3 gKV(1, Dd/128, Bb*KVS);
    const long wDD = (long)2*Dd*Dd, wPD = (long)2*Pp*Dd, wDF = (long)2*DFf*Dd;

    // launch order: gemm_mma V (l=0) at launch index 3 so ncu captures a GEMM
    embed_kernel<<<BS,256>>>(x, emb, pos, hS);                          // 0
    wconv<<<dim3(Dd/32, Dd/32, Ll), wt>>>(Wv, wv, Dd, Dd);              // 1
    wfold<<<dim3(Pp/32, Dd/32, 2*Ll), wt>>>(Wq, Wk, Wf, wqf, wkf);      // 2
    gemm_mma<0,1,0,0><<<gDD,256,SMEM3>>>(hS, 16, wv, 16, 0, bv, nullptr, vT, Dd, Dd);  // 3 (l=0 V)
    bfold<<<2*Ll, dim3(128,8)>>>(bq, bk, bf, Wf, bqf, bkf);             // 4
    wconv<<<dim3(Dd/32, Dd/32, Ll), wt>>>(Wo, wo, Dd, Dd);              // 5
    wconv_h<<<dim3(DFf/32, Dd/32,  Ll), wt>>>(W1, w1, Dd, DFf);         // 6
    wconv_h<<<dim3(Dd/32,  DFf/32, Ll), wt>>>(W2, w2, DFf, Dd);         // 7

    for (int l = 0; l < Ll; l++){
        if (l > 0)
            gemm_mma<0,1,0,0><<<gDD,256,SMEM3>>>(hS, 16, wv + l*wDD, 16, 0, bv + l*Dd, nullptr, vT, Dd, Dd);
        gemm_mma<1,0,0,0><<<gDP,256,SMEM3>>>(hS, 16, wqf + l*wPD, 16, 0, bqf + l*Pp, nullptr, pqS, Pp, Dd);
        gemm_mma<1,1,0,0><<<gDP,256,SMEM3>>>(hS, 16, wkf + l*wPD, 16, 0, bkf + l*Pp, nullptr, pkT, Pp, Dd);
        ksum_kernel<<<dim3(Pp,Bb),256>>>(pkT, ks);
        gemm_kv<<<gKV,256,SMEM3>>>(vT, pkT, kvp);
        reduce_kvt<<<(Bb*Dd*Pp)/256,256>>>(kvp, kvtS);
        z_kernel<<<BS/8,256>>>(pqS, ks, z);
        gemm_mma<3,0,0,0><<<gAT,256,SMEM3>>>(pqS, 4, kvtS, 4, (long)2*Dd*Pp, nullptr, z, tS, Dd, Pp);
        gemm_mma<0,0,0,0><<<gDD,256,SMEM3>>>(tS, 16, wo + l*wDD, 16, 0, bo + l*Dd, nullptr, qS, Dd, Dd);
        ln_kernel<<<BS,256>>>(qS, lng + l*Dd, lnb + l*Dd, tS);
        gemm_mma<2,0,1,1><<<gDF,256,SMEM2>>>(tS, 16, w1 + l*wDF, 16, 0, b1 + l*DFf, nullptr, mS, DFf, Dd);
        gemm_mma<0,0,1,0><<<gDD,256,SMEM2>>>(mS, 64, w2 + l*wDF, 64, 0, b2 + l*Dd, nullptr, hS, Dd, DFf);
    }

    colsum_part<<<dim3(32,Bb),Dd>>>(hS, pp);
    colsum_fin <<<Bb,Dd>>>(pp, pool, Dd, 32, 1.0f/Ss);
    head1_kernel<<<Bb,DHh>>>(pool, Wh1, bh1, h1);
    head2_kernel<<<1,32>>>(h1, Wh2, bh2, (float*)d_out);
}